// round 8
// baseline (speedup 1.0000x reference)
#include <cuda_runtime.h>
#include <cuda_fp16.h>
#include <cstddef>
#include <cstdint>

#define L   2048
#define D   1024
#define H   16
#define KS  1024
#define VS  1024
#define HID 4096
#define HD  64

// ---------------- scratch (device globals; no allocation allowed) ----------
__device__ float g_q[L * KS];                 // 8 MB
__device__ float g_k[L * KS];                 // 8 MB
__device__ float g_v[L * VS];                 // 8 MB
__device__ float g_vt[VS * L];                // 8 MB (V transposed)
__device__ float g_t0[L * HID];               // 32 MB (qkv stage-1 slices / FFN hidden)
__device__ float g_att[(size_t)H * L * L];    // 256 MB
__device__ float g_sp[L * L];                 // 16 MB
__device__ float g_o[L * VS];                 // 8 MB
__device__ float g_h[L * D];                  // 8 MB
__device__ float g_f[L * D];                  // 8 MB

// ---------------- helpers ---------------------------------------------------
__device__ __forceinline__ unsigned pack2h(float lo, float hi) {
    __half2 h = __floats2half2_rn(lo, hi);   // low half <- lo
    return *(unsigned*)&h;
}

// m16n8k16 fp16 MMA, fp32 accumulate (fp16 mantissa == tf32 mantissa)
__device__ __forceinline__ void mma_f16(float* c, const unsigned* a, const unsigned* b) {
    asm volatile(
        "mma.sync.aligned.m16n8k16.row.col.f32.f16.f16.f32 "
        "{%0,%1,%2,%3}, {%4,%5,%6,%7}, {%8,%9}, {%0,%1,%2,%3};\n"
        : "+f"(c[0]), "+f"(c[1]), "+f"(c[2]), "+f"(c[3])
        : "r"(a[0]), "r"(a[1]), "r"(a[2]), "r"(a[3]), "r"(b[0]), "r"(b[1]));
}

__device__ __forceinline__ void cp16(unsigned dst, const void* src) {
    asm volatile("cp.async.ca.shared.global [%0], [%1], 16;\n" :: "r"(dst), "l"(src));
}
#define CP_COMMIT() asm volatile("cp.async.commit_group;\n" ::: "memory")
#define CP_WAIT1()  asm volatile("cp.async.wait_group 1;\n" ::: "memory")
#define CP_WAIT0()  asm volatile("cp.async.wait_group 0;\n" ::: "memory")

__device__ __forceinline__ float warpRedSum(float v) {
#pragma unroll
    for (int o = 16; o > 0; o >>= 1) v += __shfl_xor_sync(0xffffffffu, v, o);
    return v;
}
__device__ __forceinline__ float warpRedMax(float v) {
#pragma unroll
    for (int o = 16; o > 0; o >>= 1) v = fmaxf(v, __shfl_xor_sync(0xffffffffu, v, o));
    return v;
}
__device__ __forceinline__ float blockRedSum(float v, float* sred) {
    int lane = threadIdx.x & 31, w = threadIdx.x >> 5;
    v = warpRedSum(v);
    if (lane == 0) sred[w] = v;
    __syncthreads();
    float r;
    if (threadIdx.x < 32) {
        r = (threadIdx.x < 8) ? sred[threadIdx.x] : 0.0f;
        r = warpRedSum(r);
        if (threadIdx.x == 0) sred[0] = r;
    }
    __syncthreads();
    r = sred[0];
    __syncthreads();
    return r;
}
__device__ __forceinline__ float blockRedMax(float v, float* sred) {
    int lane = threadIdx.x & 31, w = threadIdx.x >> 5;
    v = warpRedMax(v);
    if (lane == 0) sred[w] = v;
    __syncthreads();
    float r;
    if (threadIdx.x < 32) {
        r = (threadIdx.x < 8) ? sred[threadIdx.x] : -3.4e38f;
        r = warpRedMax(r);
        if (threadIdx.x == 0) sred[0] = r;
    }
    __syncthreads();
    r = sred[0];
    __syncthreads();
    return r;
}

// ---------------- FP16 NT GEMM body: 128x128 tile, BK=16, 512 threads -------
// Warps 4(m) x 4(n); warp tile 32x32: 2 m16-tiles x 4 n8-tiles, one k16 MMA
// per K-step per tile pair. cp.async double-buffered; fp32 in smem, fp16
// pack at fragment load.
template <int RELU>
__device__ __forceinline__ void gemm_body(const float* __restrict__ A,
                                          const float* __restrict__ W,
                                          const float* __restrict__ bias,
                                          float* __restrict__ C, int N, int K) {
    __shared__ float As[2][128][20];
    __shared__ float Ws[2][128][20];
    int tid = threadIdx.x;
    int wid = tid >> 5, lane = tid & 31;
    int g = lane >> 2, c = lane & 3;
    int wm = wid >> 2, wn = wid & 3;
    int bm = blockIdx.y * 128, bn = blockIdx.x * 128;

    float acc[2][4][4] = {};

    int lrow = tid >> 2;            // 0..127
    int lcol = (tid & 3) << 2;      // 0,4,8,12
    const float* Ap = A + (size_t)(bm + lrow) * K + lcol;
    const float* Wp = W + (size_t)(bn + lrow) * K + lcol;

    unsigned da0 = (unsigned)__cvta_generic_to_shared(&As[0][lrow][lcol]);
    unsigned dw0 = (unsigned)__cvta_generic_to_shared(&Ws[0][lrow][lcol]);
    const unsigned stage_off = 128 * 20 * 4;

    cp16(da0, Ap);
    cp16(dw0, Wp);
    CP_COMMIT();

    for (int k0 = 0; k0 < K; k0 += 16) {
        int s = (k0 >> 4) & 1;
        if (k0 + 16 < K) {
            cp16(da0 + (s ^ 1) * stage_off, Ap + k0 + 16);
            cp16(dw0 + (s ^ 1) * stage_off, Wp + k0 + 16);
            CP_COMMIT();
            CP_WAIT1();
        } else {
            CP_WAIT0();
        }
        __syncthreads();
        unsigned af[2][4], bf[4][2];
#pragma unroll
        for (int mt = 0; mt < 2; mt++) {
            int rm = wm * 32 + mt * 16 + g;
            float2 x0 = *(const float2*)&As[s][rm][2 * c];
            float2 x1 = *(const float2*)&As[s][rm + 8][2 * c];
            float2 x2 = *(const float2*)&As[s][rm][2 * c + 8];
            float2 x3 = *(const float2*)&As[s][rm + 8][2 * c + 8];
            af[mt][0] = pack2h(x0.x, x0.y);
            af[mt][1] = pack2h(x1.x, x1.y);
            af[mt][2] = pack2h(x2.x, x2.y);
            af[mt][3] = pack2h(x3.x, x3.y);
        }
#pragma unroll
        for (int nt = 0; nt < 4; nt++) {
            int rn = wn * 32 + nt * 8 + g;
            float2 y0 = *(const float2*)&Ws[s][rn][2 * c];
            float2 y1 = *(const float2*)&Ws[s][rn][2 * c + 8];
            bf[nt][0] = pack2h(y0.x, y0.y);
            bf[nt][1] = pack2h(y1.x, y1.y);
        }
#pragma unroll
        for (int mt = 0; mt < 2; mt++)
#pragma unroll
            for (int nt = 0; nt < 4; nt++)
                mma_f16(acc[mt][nt], af[mt], bf[nt]);
        __syncthreads();
    }
#pragma unroll
    for (int mt = 0; mt < 2; mt++) {
        int row = bm + wm * 32 + mt * 16 + g;
#pragma unroll
        for (int nt = 0; nt < 4; nt++) {
            int col = bn + wn * 32 + nt * 8 + 2 * c;
            float2 bv = *(const float2*)&bias[col];
            float v0 = acc[mt][nt][0] + bv.x;
            float v1 = acc[mt][nt][1] + bv.y;
            float v2 = acc[mt][nt][2] + bv.x;
            float v3 = acc[mt][nt][3] + bv.y;
            if (RELU) {
                v0 = fmaxf(v0, 0.0f); v1 = fmaxf(v1, 0.0f);
                v2 = fmaxf(v2, 0.0f); v3 = fmaxf(v3, 0.0f);
            }
            *(float2*)&C[(size_t)row * N + col] = make_float2(v0, v1);
            *(float2*)&C[(size_t)(row + 8) * N + col] = make_float2(v2, v3);
        }
    }
}

template <int RELU>
__global__ void __launch_bounds__(512)
gemm_tc(const float* __restrict__ A, const float* __restrict__ W,
        const float* __restrict__ bias, float* __restrict__ C, int N, int K) {
    gemm_body<RELU>(A, W, bias, C, N, K);
}

// Merged 3-way GEMM: blockIdx.z selects (A, W, bias, C).
__global__ void __launch_bounds__(512)
gemm_tc3(const float* __restrict__ A0, const float* __restrict__ A1,
         const float* __restrict__ A2,
         const float* __restrict__ W0, const float* __restrict__ W1,
         const float* __restrict__ W2,
         const float* __restrict__ b0, const float* __restrict__ b1,
         const float* __restrict__ b2,
         float* __restrict__ C0, float* __restrict__ C1, float* __restrict__ C2,
         int N, int K) {
    int z = blockIdx.z;
    const float* A = (z == 0) ? A0 : (z == 1) ? A1 : A2;
    const float* W = (z == 0) ? W0 : (z == 1) ? W1 : W2;
    const float* b = (z == 0) ? b0 : (z == 1) ? b1 : b2;
    float* C = (z == 0) ? C0 : (z == 1) ? C1 : C2;
    gemm_body<0>(A, W, b, C, N, K);
}

// ---------------- attention scores (FP16 MMA) -------------------------------
// att[h] = q_h @ k_h^T * 0.125 + sp. 256 threads, warps 2(m)x4(n),
// warp tile 64x32 (4 m-tiles x 4 n-tiles). K=64: 4 k16 chunks.
__global__ void attn_scores_tc(const float* __restrict__ q, const float* __restrict__ k,
                               const float* __restrict__ sp, float* __restrict__ att) {
    __shared__ float As[128][20];
    __shared__ float Ws[128][20];
    int h = blockIdx.z;
    int tid = threadIdx.x;
    int wid = tid >> 5, lane = tid & 31;
    int g = lane >> 2, c = lane & 3;
    int wm = wid >> 2, wn = wid & 3;
    int bm = blockIdx.y * 128, bn = blockIdx.x * 128;

    float acc[4][4][4] = {};

    int lr = tid >> 1, lkc = (tid & 1) * 8;
    const float* Ap = q + h * HD + (size_t)(bm + lr) * KS + lkc;
    const float* Wp = k + h * HD + (size_t)(bn + lr) * KS + lkc;

    for (int k0 = 0; k0 < HD; k0 += 16) {
        float4 a0 = *(const float4*)(Ap + k0);
        float4 a1 = *(const float4*)(Ap + k0 + 4);
        float4 w0 = *(const float4*)(Wp + k0);
        float4 w1 = *(const float4*)(Wp + k0 + 4);
        *(float4*)&As[lr][lkc]     = a0;
        *(float4*)&As[lr][lkc + 4] = a1;
        *(float4*)&Ws[lr][lkc]     = w0;
        *(float4*)&Ws[lr][lkc + 4] = w1;
        __syncthreads();
        unsigned af[4][4], bf[4][2];
#pragma unroll
        for (int mt = 0; mt < 4; mt++) {
            int rm = wm * 64 + mt * 16 + g;
            float2 x0 = *(const float2*)&As[rm][2 * c];
            float2 x1 = *(const float2*)&As[rm + 8][2 * c];
            float2 x2 = *(const float2*)&As[rm][2 * c + 8];
            float2 x3 = *(const float2*)&As[rm + 8][2 * c + 8];
            af[mt][0] = pack2h(x0.x, x0.y);
            af[mt][1] = pack2h(x1.x, x1.y);
            af[mt][2] = pack2h(x2.x, x2.y);
            af[mt][3] = pack2h(x3.x, x3.y);
        }
#pragma unroll
        for (int nt = 0; nt < 4; nt++) {
            int rn = wn * 32 + nt * 8 + g;
            float2 y0 = *(const float2*)&Ws[rn][2 * c];
            float2 y1 = *(const float2*)&Ws[rn][2 * c + 8];
            bf[nt][0] = pack2h(y0.x, y0.y);
            bf[nt][1] = pack2h(y1.x, y1.y);
        }
#pragma unroll
        for (int mt = 0; mt < 4; mt++)
#pragma unroll
            for (int nt = 0; nt < 4; nt++)
                mma_f16(acc[mt][nt], af[mt], bf[nt]);
        __syncthreads();
    }
    size_t base = (size_t)h * L * L;
#pragma unroll
    for (int mt = 0; mt < 4; mt++) {
        int row = bm + wm * 64 + mt * 16 + g;
#pragma unroll
        for (int nt = 0; nt < 4; nt++) {
            int col = bn + wn * 32 + nt * 8 + 2 * c;
            float2 s0 = *(const float2*)&sp[(size_t)row * L + col];
            float2 s1 = *(const float2*)&sp[(size_t)(row + 8) * L + col];
            *(float2*)&att[base + (size_t)row * L + col] =
                make_float2(acc[mt][nt][0] * 0.125f + s0.x, acc[mt][nt][1] * 0.125f + s0.y);
            *(float2*)&att[base + (size_t)(row + 8) * L + col] =
                make_float2(acc[mt][nt][2] * 0.125f + s1.x, acc[mt][nt][3] * 0.125f + s1.y);
        }
    }
}

// ---------------- AV (FP16 MMA, cp.async pipelined) -------------------------
// o[:, h*64:+64] = att[h] @ vt_h^T. vt: [VS, L]. 128x64 tile, 256 threads.
// Warps 4(m) x 2(n); warp tile 32x32: 2 m-tiles x 4 n-tiles, k16 chunks.
__global__ void __launch_bounds__(256)
attn_av_tc(const float* __restrict__ att, const float* __restrict__ vt,
           float* __restrict__ o) {
    __shared__ float As[2][128][20];
    __shared__ float Ws[2][64][20];
    int h = blockIdx.z;
    int tid = threadIdx.x;
    int wid = tid >> 5, lane = tid & 31;
    int g = lane >> 2, c = lane & 3;
    int wm = wid >> 1, wn = wid & 1;
    int bm = blockIdx.y * 128;

    float acc[2][4][4] = {};

    int lr = tid >> 1, lcol = (tid & 1) * 8;
    const float* Ap = att + (size_t)h * L * L + (size_t)(bm + lr) * L + lcol;
    int wr = tid >> 2, wkc = (tid & 3) * 4;
    const float* Wp = vt + (size_t)(h * HD + wr) * L + wkc;

    unsigned da0 = (unsigned)__cvta_generic_to_shared(&As[0][lr][lcol]);
    unsigned dw0 = (unsigned)__cvta_generic_to_shared(&Ws[0][wr][wkc]);
    const unsigned a_off = 128 * 20 * 4;
    const unsigned w_off = 64 * 20 * 4;

    cp16(da0, Ap);    cp16(da0 + 16, Ap + 4);
    cp16(dw0, Wp);
    CP_COMMIT();

    for (int k0 = 0; k0 < L; k0 += 16) {
        int s = (k0 >> 4) & 1;
        if (k0 + 16 < L) {
            cp16(da0 + (s ^ 1) * a_off, Ap + k0 + 16);
            cp16(da0 + (s ^ 1) * a_off + 16, Ap + k0 + 20);
            cp16(dw0 + (s ^ 1) * w_off, Wp + k0 + 16);
            CP_COMMIT();
            CP_WAIT1();
        } else {
            CP_WAIT0();
        }
        __syncthreads();
        unsigned af[2][4], bf[4][2];
#pragma unroll
        for (int mt = 0; mt < 2; mt++) {
            int rm = wm * 32 + mt * 16 + g;
            float2 x0 = *(const float2*)&As[s][rm][2 * c];
            float2 x1 = *(const float2*)&As[s][rm + 8][2 * c];
            float2 x2 = *(const float2*)&As[s][rm][2 * c + 8];
            float2 x3 = *(const float2*)&As[s][rm + 8][2 * c + 8];
            af[mt][0] = pack2h(x0.x, x0.y);
            af[mt][1] = pack2h(x1.x, x1.y);
            af[mt][2] = pack2h(x2.x, x2.y);
            af[mt][3] = pack2h(x3.x, x3.y);
        }
#pragma unroll
        for (int nt = 0; nt < 4; nt++) {
            int rn = wn * 32 + nt * 8 + g;
            float2 y0 = *(const float2*)&Ws[s][rn][2 * c];
            float2 y1 = *(const float2*)&Ws[s][rn][2 * c + 8];
            bf[nt][0] = pack2h(y0.x, y0.y);
            bf[nt][1] = pack2h(y1.x, y1.y);
        }
#pragma unroll
        for (int mt = 0; mt < 2; mt++)
#pragma unroll
            for (int nt = 0; nt < 4; nt++)
                mma_f16(acc[mt][nt], af[mt], bf[nt]);
        __syncthreads();
    }
#pragma unroll
    for (int mt = 0; mt < 2; mt++) {
        int row = bm + wm * 32 + mt * 16 + g;
#pragma unroll
        for (int nt = 0; nt < 4; nt++) {
            int col = h * HD + wn * 32 + nt * 8 + 2 * c;
            *(float2*)&o[(size_t)row * VS + col] =
                make_float2(acc[mt][nt][0], acc[mt][nt][1]);
            *(float2*)&o[(size_t)(row + 8) * VS + col] =
                make_float2(acc[mt][nt][2], acc[mt][nt][3]);
        }
    }
}

// ---------------- transpose: out[c][r] = in[r][c]; in [R x Cc] --------------
__global__ void transpose_k(const float* __restrict__ in, float* __restrict__ out,
                            int R, int Cc) {
    __shared__ float t[32][33];
    int c0 = blockIdx.x * 32, r0 = blockIdx.y * 32;
    int tx = threadIdx.x, ty = threadIdx.y;  // 32 x 8
#pragma unroll
    for (int i = 0; i < 4; i++)
        t[ty + i * 8][tx] = in[(size_t)(r0 + ty + i * 8) * Cc + c0 + tx];
    __syncthreads();
#pragma unroll
    for (int i = 0; i < 4; i++)
        out[(size_t)(c0 + ty + i * 8) * R + r0 + tx] = t[tx][ty + i * 8];
}

// ---------------- row softmax over 2048 cols --------------------------------
__global__ void softmax_row2048(const float* __restrict__ in, float* __restrict__ out,
                                float outscale) {
    __shared__ float sred[8];
    size_t row = blockIdx.x;
    const float* p = in + row * 2048;
    float* o = out + row * 2048;
    int tid = threadIdx.x;
    float v[8];
    float4 a = *(const float4*)&p[tid * 8];
    float4 b = *(const float4*)&p[tid * 8 + 4];
    v[0] = a.x; v[1] = a.y; v[2] = a.z; v[3] = a.w;
    v[4] = b.x; v[5] = b.y; v[6] = b.z; v[7] = b.w;
    float m = v[0];
#pragma unroll
    for (int i = 1; i < 8; i++) m = fmaxf(m, v[i]);
    m = blockRedMax(m, sred);
    float s = 0.0f;
#pragma unroll
    for (int i = 0; i < 8; i++) { v[i] = __expf(v[i] - m); s += v[i]; }
    s = blockRedSum(s, sred);
    float inv = outscale / s;
    float4 oa, ob;
    oa.x = v[0] * inv; oa.y = v[1] * inv; oa.z = v[2] * inv; oa.w = v[3] * inv;
    ob.x = v[4] * inv; ob.y = v[5] * inv; ob.z = v[6] * inv; ob.w = v[7] * inv;
    *(float4*)&o[tid * 8] = oa;
    *(float4*)&o[tid * 8 + 4] = ob;
}

// ---------------- fused residual + LayerNorm --------------------------------
__global__ void add_ln(const float* __restrict__ a, const float* __restrict__ b,
                       const float* __restrict__ g, const float* __restrict__ be,
                       float* __restrict__ out) {
    __shared__ float sred[8];
    int row = blockIdx.x;
    int tid = threadIdx.x;
    size_t base = (size_t)row * 1024 + tid * 4;
    float4 va = *(const float4*)&a[base];
    float4 vb = *(const float4*)&b[base];
    float4 s;
    s.x = va.x + vb.x; s.y = va.y + vb.y; s.z = va.z + vb.z; s.w = va.w + vb.w;
    float sum = s.x + s.y + s.z + s.w;
    float sq = s.x * s.x + s.y * s.y + s.z * s.z + s.w * s.w;
    sum = blockRedSum(sum, sred);
    sq = blockRedSum(sq, sred);
    float mean = sum * (1.0f / 1024.0f);
    float var = sq * (1.0f / 1024.0f) - mean * mean;
    float r = rsqrtf(var + 1e-5f);
    float4 vg = *(const float4*)&g[tid * 4];
    float4 vbe = *(const float4*)&be[tid * 4];
    float4 o;
    o.x = (s.x - mean) * r * vg.x + vbe.x;
    o.y = (s.y - mean) * r * vg.y + vbe.y;
    o.z = (s.z - mean) * r * vg.z + vbe.z;
    o.w = (s.w - mean) * r * vg.w + vbe.w;
    *(float4*)&out[base] = o;
}

// ---------------- launch ----------------------------------------------------
extern "C" void kernel_launch(void* const* d_in, const int* in_sizes, int n_in,
                              void* d_out, int out_size) {
    const float* x   = (const float*)d_in[0];
    const float* sp  = (const float*)d_in[1];
    const float* Wq  = (const float*)d_in[2];
    const float* bq  = (const float*)d_in[3];
    const float* Wk  = (const float*)d_in[4];
    const float* bk  = (const float*)d_in[5];
    const float* Wv  = (const float*)d_in[6];
    const float* bv  = (const float*)d_in[7];
    const float* Wqp = (const float*)d_in[8];
    const float* bqp = (const float*)d_in[9];
    const float* Wkp = (const float*)d_in[10];
    const float* bkp = (const float*)d_in[11];
    const float* Wvp = (const float*)d_in[12];
    const float* bvp = (const float*)d_in[13];
    const float* Wo  = (const float*)d_in[14];
    const float* bo  = (const float*)d_in[15];
    const float* W1  = (const float*)d_in[16];
    const float* b1  = (const float*)d_in[17];
    const float* W2  = (const float*)d_in[18];
    const float* b2  = (const float*)d_in[19];
    const float* g1  = (const float*)d_in[20];
    const float* be1 = (const float*)d_in[21];
    const float* g2  = (const float*)d_in[22];
    const float* be2 = (const float*)d_in[23];
    float* out = (float*)d_out;

    float *pq, *pk, *pv, *pvt, *pt0, *patt, *psp, *po, *ph, *pf;
    cudaGetSymbolAddress((void**)&pq,  g_q);
    cudaGetSymbolAddress((void**)&pk,  g_k);
    cudaGetSymbolAddress((void**)&pv,  g_v);
    cudaGetSymbolAddress((void**)&pvt, g_vt);
    cudaGetSymbolAddress((void**)&pt0, g_t0);
    cudaGetSymbolAddress((void**)&patt, g_att);
    cudaGetSymbolAddress((void**)&psp, g_sp);
    cudaGetSymbolAddress((void**)&po,  g_o);
    cudaGetSymbolAddress((void**)&ph,  g_h);
    cudaGetSymbolAddress((void**)&pf,  g_f);

    float* t0a = pt0;
    float* t0b = pt0 + (size_t)L * KS;
    float* t0c = pt0 + (size_t)2 * L * KS;

    dim3 blk256(256), blk512(512);

    // QKV stage-1 (shared A = x), merged into one launch
    gemm_tc3<<<dim3(KS / 128, L / 128, 3), blk512>>>(
        x, x, x, Wq, Wk, Wv, bq, bk, bv, t0a, t0b, t0c, KS, D);
    // QKV stage-2, merged
    gemm_tc3<<<dim3(KS / 128, L / 128, 3), blk512>>>(
        t0a, t0b, t0c, Wqp, Wkp, Wvp, bqp, bkp, bvp, pq, pk, pv, KS, KS);

    // v transpose for AV mma
    transpose_k<<<dim3(VS / 32, L / 32), dim3(32, 8)>>>(pv, pvt, L, VS);

    // sp_bias = 0.5 * softmax(shortest_path, axis=-1)
    softmax_row2048<<<L, blk256>>>(sp, psp, 0.5f);

    // att = softmax(qk^T/8 + sp_bias)
    attn_scores_tc<<<dim3(L / 128, L / 128, H), blk256>>>(pq, pk, psp, patt);
    softmax_row2048<<<H * L, blk256>>>(patt, patt, 1.0f);

    // context = att @ v
    attn_av_tc<<<dim3(1, L / 128, H), blk256>>>(patt, pvt, po);

    // o-proj, residual + LN1
    gemm_tc<0><<<dim3(D / 128, L / 128), blk512>>>(po, Wo, bo, pf, D, VS);
    add_ln<<<L, blk256>>>(x, pf, g1, be1, ph);

    // FFN, residual + LN2
    gemm_tc<1><<<dim3(HID / 128, L / 128), blk512>>>(ph, W1, b1, pt0, HID, D);
    gemm_tc<1><<<dim3(D / 128, L / 128), blk512>>>(pt0, W2, b2, pf, D, HID);
    add_ln<<<L, blk256>>>(ph, pf, g2, be2, out);
}

// round 11
// speedup vs baseline: 1.7317x; 1.7317x over previous
#include <cuda_runtime.h>
#include <cuda_fp16.h>
#include <cstddef>
#include <cstdint>

#define L   2048
#define D   1024
#define H   16
#define KS  1024
#define VS  1024
#define HID 4096
#define HD  64

// ---------------- scratch (device globals; no allocation allowed) ----------
__device__ __half g_xh[L * D];
__device__ __half g_wqh[KS * D];
__device__ __half g_wkh[KS * D];
__device__ __half g_wvh[VS * D];
__device__ __half g_wqph[KS * KS];
__device__ __half g_wkph[KS * KS];
__device__ __half g_wvph[VS * VS];
__device__ __half g_woh[D * VS];
__device__ __half g_w1h[HID * D];
__device__ __half g_w2h[D * HID];
__device__ __half g_t0h[L * HID];              // qkv stage-1 (3 slices) / FFN hidden
__device__ __half g_qh[L * KS];
__device__ __half g_kh[L * KS];
__device__ __half g_vh[L * VS];
__device__ __half g_vth[VS * L];
__device__ __half g_att16[(size_t)H * L * L];  // 128 MB unnormalized probs (fp16)
__device__ float  g_ssum[H * L];               // per-(h,row) softmax denominators
__device__ __half g_oh[L * VS];
__device__ __half g_hh[L * D];
__device__ float  g_sp[L * L];
__device__ float  g_h[L * D];
__device__ float  g_f[L * D];

// ---------------- helpers ---------------------------------------------------
// m16n8k16 fp16 MMA, fp32 accumulate
__device__ __forceinline__ void mma_f16(float* c, const unsigned* a, const unsigned* b) {
    asm volatile(
        "mma.sync.aligned.m16n8k16.row.col.f32.f16.f16.f32 "
        "{%0,%1,%2,%3}, {%4,%5,%6,%7}, {%8,%9}, {%0,%1,%2,%3};\n"
        : "+f"(c[0]), "+f"(c[1]), "+f"(c[2]), "+f"(c[3])
        : "r"(a[0]), "r"(a[1]), "r"(a[2]), "r"(a[3]), "r"(b[0]), "r"(b[1]));
}

__device__ __forceinline__ void cp16(unsigned dst, const void* src) {
    asm volatile("cp.async.ca.shared.global [%0], [%1], 16;\n" :: "r"(dst), "l"(src));
}
#define CP_COMMIT() asm volatile("cp.async.commit_group;\n" ::: "memory")
#define CP_WAIT1()  asm volatile("cp.async.wait_group 1;\n" ::: "memory")
#define CP_WAIT0()  asm volatile("cp.async.wait_group 0;\n" ::: "memory")

__device__ __forceinline__ float warpRedSum(float v) {
#pragma unroll
    for (int o = 16; o > 0; o >>= 1) v += __shfl_xor_sync(0xffffffffu, v, o);
    return v;
}
__device__ __forceinline__ float warpRedMax(float v) {
#pragma unroll
    for (int o = 16; o > 0; o >>= 1) v = fmaxf(v, __shfl_xor_sync(0xffffffffu, v, o));
    return v;
}
__device__ __forceinline__ float blockRedSum(float v, float* sred) {
    int lane = threadIdx.x & 31, w = threadIdx.x >> 5;
    v = warpRedSum(v);
    if (lane == 0) sred[w] = v;
    __syncthreads();
    float r;
    if (threadIdx.x < 32) {
        r = (threadIdx.x < 8) ? sred[threadIdx.x] : 0.0f;
        r = warpRedSum(r);
        if (threadIdx.x == 0) sred[0] = r;
    }
    __syncthreads();
    r = sred[0];
    __syncthreads();
    return r;
}
__device__ __forceinline__ float blockRedMax(float v, float* sred) {
    int lane = threadIdx.x & 31, w = threadIdx.x >> 5;
    v = warpRedMax(v);
    if (lane == 0) sred[w] = v;
    __syncthreads();
    float r;
    if (threadIdx.x < 32) {
        r = (threadIdx.x < 8) ? sred[threadIdx.x] : -3.4e38f;
        r = warpRedMax(r);
        if (threadIdx.x == 0) sred[0] = r;
    }
    __syncthreads();
    r = sred[0];
    __syncthreads();
    return r;
}

// ---------------- fp32 -> fp16 converter ------------------------------------
__global__ void f2h(const float* __restrict__ in, __half* __restrict__ out, int n) {
    int i = (blockIdx.x * blockDim.x + threadIdx.x) * 4;
    if (i < n) {
        float4 v = *(const float4*)&in[i];
        *(__half2*)&out[i]     = __floats2half2_rn(v.x, v.y);
        *(__half2*)&out[i + 2] = __floats2half2_rn(v.z, v.w);
    }
}

// ---------------- FP16 NT GEMM body: 128x128 tile, BK=32 halves, 512 thr ----
template <int RELU, int OUT_HALF>
__device__ __forceinline__ void gemm_body(const __half* __restrict__ A,
                                          const __half* __restrict__ W,
                                          const float* __restrict__ bias,
                                          void* __restrict__ Cv, int N, int K) {
    __shared__ unsigned As[2][128][20];   // 16 data uints (32 halves) + 4 pad
    __shared__ unsigned Ws[2][128][20];
    int tid = threadIdx.x;
    int wid = tid >> 5, lane = tid & 31;
    int g = lane >> 2, c = lane & 3;
    int wm = wid >> 2, wn = wid & 3;
    int bm = blockIdx.y * 128, bn = blockIdx.x * 128;

    float acc[2][4][4] = {};

    int lrow = tid >> 2;            // 0..127
    int lcu = (tid & 3) * 4;        // uint col: 0,4,8,12 (16B chunks)
    const __half* Ap = A + (size_t)(bm + lrow) * K + lcu * 2;
    const __half* Wp = W + (size_t)(bn + lrow) * K + lcu * 2;

    unsigned da0 = (unsigned)__cvta_generic_to_shared(&As[0][lrow][lcu]);
    unsigned dw0 = (unsigned)__cvta_generic_to_shared(&Ws[0][lrow][lcu]);
    const unsigned stage_off = 128 * 20 * 4;

    cp16(da0, Ap);
    cp16(dw0, Wp);
    CP_COMMIT();

    for (int k0 = 0; k0 < K; k0 += 32) {      // halves
        int s = (k0 >> 5) & 1;
        if (k0 + 32 < K) {
            cp16(da0 + (s ^ 1) * stage_off, Ap + k0 + 32);
            cp16(dw0 + (s ^ 1) * stage_off, Wp + k0 + 32);
            CP_COMMIT();
            CP_WAIT1();
        } else {
            CP_WAIT0();
        }
        __syncthreads();
#pragma unroll
        for (int kc = 0; kc < 2; kc++) {      // two k16 chunks per 32-half step
            int kk = kc * 8;                  // uint offset
            unsigned af[2][4], bf[4][2];
#pragma unroll
            for (int mt = 0; mt < 2; mt++) {
                int rm = wm * 32 + mt * 16 + g;
                af[mt][0] = As[s][rm][kk + c];
                af[mt][1] = As[s][rm + 8][kk + c];
                af[mt][2] = As[s][rm][kk + c + 4];
                af[mt][3] = As[s][rm + 8][kk + c + 4];
            }
#pragma unroll
            for (int nt = 0; nt < 4; nt++) {
                int rn = wn * 32 + nt * 8 + g;
                bf[nt][0] = Ws[s][rn][kk + c];
                bf[nt][1] = Ws[s][rn][kk + c + 4];
            }
#pragma unroll
            for (int mt = 0; mt < 2; mt++)
#pragma unroll
                for (int nt = 0; nt < 4; nt++)
                    mma_f16(acc[mt][nt], af[mt], bf[nt]);
        }
        __syncthreads();
    }
#pragma unroll
    for (int mt = 0; mt < 2; mt++) {
        int row = bm + wm * 32 + mt * 16 + g;
#pragma unroll
        for (int nt = 0; nt < 4; nt++) {
            int col = bn + wn * 32 + nt * 8 + 2 * c;
            float2 bv = *(const float2*)&bias[col];
            float v0 = acc[mt][nt][0] + bv.x;
            float v1 = acc[mt][nt][1] + bv.y;
            float v2 = acc[mt][nt][2] + bv.x;
            float v3 = acc[mt][nt][3] + bv.y;
            if (RELU) {
                v0 = fmaxf(v0, 0.0f); v1 = fmaxf(v1, 0.0f);
                v2 = fmaxf(v2, 0.0f); v3 = fmaxf(v3, 0.0f);
            }
            if (OUT_HALF) {
                __half* Ch = (__half*)Cv;
                *(__half2*)&Ch[(size_t)row * N + col] = __floats2half2_rn(v0, v1);
                *(__half2*)&Ch[(size_t)(row + 8) * N + col] = __floats2half2_rn(v2, v3);
            } else {
                float* Cf = (float*)Cv;
                *(float2*)&Cf[(size_t)row * N + col] = make_float2(v0, v1);
                *(float2*)&Cf[(size_t)(row + 8) * N + col] = make_float2(v2, v3);
            }
        }
    }
}

template <int RELU, int OUT_HALF>
__global__ void __launch_bounds__(512)
gemm_tc(const __half* __restrict__ A, const __half* __restrict__ W,
        const float* __restrict__ bias, void* __restrict__ C, int N, int K) {
    gemm_body<RELU, OUT_HALF>(A, W, bias, C, N, K);
}

// Merged 3-way GEMM (fp16 out): blockIdx.z selects operands.
__global__ void __launch_bounds__(512)
gemm_tc3(const __half* __restrict__ A0, const __half* __restrict__ A1,
         const __half* __restrict__ A2,
         const __half* __restrict__ W0, const __half* __restrict__ W1,
         const __half* __restrict__ W2,
         const float* __restrict__ b0, const float* __restrict__ b1,
         const float* __restrict__ b2,
         __half* __restrict__ C0, __half* __restrict__ C1, __half* __restrict__ C2,
         int N, int K) {
    int z = blockIdx.z;
    const __half* A = (z == 0) ? A0 : (z == 1) ? A1 : A2;
    const __half* W = (z == 0) ? W0 : (z == 1) ? W1 : W2;
    const float* b = (z == 0) ? b0 : (z == 1) ? b1 : b2;
    __half* C = (z == 0) ? C0 : (z == 1) ? C1 : C2;
    gemm_body<0, 1>(A, W, b, (void*)C, N, K);
}

// ---------------- fused scores + softmax (flash-style, two passes) ----------
// For 16 q-rows of head h: pass 1 computes row maxima of (q k^T/8 + sp_bias)
// via MMA sweep over K; pass 2 recomputes, writes UNNORMALIZED exp(l - m) as
// fp16 probs, and stores the fp32 row sums (applied in the AV epilogue).
// grid (L/16, H), 256 threads = 8 warps; warp w owns cols [w*16, w*16+16).
__global__ void __launch_bounds__(256)
attn_scores_softmax(const __half* __restrict__ q, const __half* __restrict__ k,
                    const float* __restrict__ sp, __half* __restrict__ probs,
                    float* __restrict__ ssum) {
    __shared__ unsigned Qs[16][36];    // 16 rows x 32 uints (64 halves) + pad
    __shared__ unsigned Ks[128][36];   // K chunk: 128 rows x 64 halves
    __shared__ float red[8][16];
    __shared__ float mrow[16];
    int tid = threadIdx.x;
    int w = tid >> 5, lane = tid & 31;
    int g = lane >> 2, c = lane & 3;
    int h = blockIdx.y;
    int bm = blockIdx.x * 16;

    if (tid < 128) {
        int r = tid >> 3, ch = tid & 7;
        *(uint4*)&Qs[r][ch * 4] =
            *(const uint4*)&q[(size_t)(bm + r) * KS + h * HD + ch * 8];
    }
    __syncthreads();

    unsigned af[4][4];
#pragma unroll
    for (int kc = 0; kc < 4; kc++) {
        int kk = kc * 8;
        af[kc][0] = Qs[g][kk + c];
        af[kc][1] = Qs[g + 8][kk + c];
        af[kc][2] = Qs[g][kk + c + 4];
        af[kc][3] = Qs[g + 8][kk + c + 4];
    }

    const float* sp0 = sp + (size_t)(bm + g) * L;
    const float* sp1 = sp + (size_t)(bm + g + 8) * L;

    // -------- pass 1: row maxima --------
    float pm0 = -3.4e38f, pm1 = -3.4e38f;
    for (int nb = 0; nb < 16; nb++) {
        __syncthreads();
        for (int i = tid; i < 1024; i += 256) {
            int r = i >> 3, ch = i & 7;
            *(uint4*)&Ks[r][ch * 4] =
                *(const uint4*)&k[(size_t)(nb * 128 + r) * KS + h * HD + ch * 8];
        }
        __syncthreads();
        float acc[2][4] = {};
#pragma unroll
        for (int kc = 0; kc < 4; kc++) {
            int kk = kc * 8;
#pragma unroll
            for (int nt = 0; nt < 2; nt++) {
                int rn = w * 16 + nt * 8 + g;
                unsigned bf[2] = {Ks[rn][kk + c], Ks[rn][kk + c + 4]};
                mma_f16(acc[nt], af[kc], bf);
            }
        }
#pragma unroll
        for (int nt = 0; nt < 2; nt++) {
            int col = nb * 128 + w * 16 + nt * 8 + 2 * c;
            float2 s0 = *(const float2*)&sp0[col];
            float2 s1 = *(const float2*)&sp1[col];
            pm0 = fmaxf(pm0, fmaxf(acc[nt][0] * 0.125f + s0.x,
                                   acc[nt][1] * 0.125f + s0.y));
            pm1 = fmaxf(pm1, fmaxf(acc[nt][2] * 0.125f + s1.x,
                                   acc[nt][3] * 0.125f + s1.y));
        }
    }
    pm0 = fmaxf(pm0, __shfl_xor_sync(0xffffffffu, pm0, 1));
    pm0 = fmaxf(pm0, __shfl_xor_sync(0xffffffffu, pm0, 2));
    pm1 = fmaxf(pm1, __shfl_xor_sync(0xffffffffu, pm1, 1));
    pm1 = fmaxf(pm1, __shfl_xor_sync(0xffffffffu, pm1, 2));
    if (c == 0) { red[w][g] = pm0; red[w][g + 8] = pm1; }
    __syncthreads();
    if (tid < 16) {
        float m = red[0][tid];
#pragma unroll
        for (int ww = 1; ww < 8; ww++) m = fmaxf(m, red[ww][tid]);
        mrow[tid] = m;
    }
    __syncthreads();
    float m0 = mrow[g], m1 = mrow[g + 8];

    // -------- pass 2: exp, store unnormalized probs, row sums --------
    size_t pbase = (size_t)h * L * L;
    float ps0 = 0.0f, ps1 = 0.0f;
    for (int nb = 0; nb < 16; nb++) {
        __syncthreads();
        for (int i = tid; i < 1024; i += 256) {
            int r = i >> 3, ch = i & 7;
            *(uint4*)&Ks[r][ch * 4] =
                *(const uint4*)&k[(size_t)(nb * 128 + r) * KS + h * HD + ch * 8];
        }
        __syncthreads();
        float acc[2][4] = {};
#pragma unroll
        for (int kc = 0; kc < 4; kc++) {
            int kk = kc * 8;
#pragma unroll
            for (int nt = 0; nt < 2; nt++) {
                int rn = w * 16 + nt * 8 + g;
                unsigned bf[2] = {Ks[rn][kk + c], Ks[rn][kk + c + 4]};
                mma_f16(acc[nt], af[kc], bf);
            }
        }
#pragma unroll
        for (int nt = 0; nt < 2; nt++) {
            int col = nb * 128 + w * 16 + nt * 8 + 2 * c;
            float2 s0 = *(const float2*)&sp0[col];
            float2 s1 = *(const float2*)&sp1[col];
            float e00 = __expf(acc[nt][0] * 0.125f + s0.x - m0);
            float e01 = __expf(acc[nt][1] * 0.125f + s0.y - m0);
            float e10 = __expf(acc[nt][2] * 0.125f + s1.x - m1);
            float e11 = __expf(acc[nt][3] * 0.125f + s1.y - m1);
            ps0 += e00 + e01;
            ps1 += e10 + e11;
            *(__half2*)&probs[pbase + (size_t)(bm + g) * L + col] =
                __floats2half2_rn(e00, e01);
            *(__half2*)&probs[pbase + (size_t)(bm + g + 8) * L + col] =
                __floats2half2_rn(e10, e11);
        }
    }
    ps0 += __shfl_xor_sync(0xffffffffu, ps0, 1);
    ps0 += __shfl_xor_sync(0xffffffffu, ps0, 2);
    ps1 += __shfl_xor_sync(0xffffffffu, ps1, 1);
    ps1 += __shfl_xor_sync(0xffffffffu, ps1, 2);
    __syncthreads();
    if (c == 0) { red[w][g] = ps0; red[w][g + 8] = ps1; }
    __syncthreads();
    if (tid < 16) {
        float s = 0.0f;
#pragma unroll
        for (int ww = 0; ww < 8; ww++) s += red[ww][tid];
        ssum[(size_t)h * L + bm + tid] = s;
    }
}

// ---------------- AV (fp16 probs x fp16 vt, cp.async pipelined) -------------
// o[:, h*64:+64] = (att16[h] @ vt_h^T) / ssum[row]. 128x64 tile, 256 threads.
__global__ void __launch_bounds__(256)
attn_av_tc(const __half* __restrict__ att, const __half* __restrict__ vt,
           const float* __restrict__ ssum, __half* __restrict__ o) {
    __shared__ unsigned As[2][128][20];
    __shared__ unsigned Ws[2][64][20];
    int h = blockIdx.z;
    int tid = threadIdx.x;
    int wid = tid >> 5, lane = tid & 31;
    int g = lane >> 2, c = lane & 3;
    int wm = wid >> 1, wn = wid & 1;
    int bm = blockIdx.y * 128;

    float acc[2][4][4] = {};

    int lr = tid >> 1;
    int lcu = (tid & 1) * 8;                 // uint cols 0 or 8 (two 16B chunks)
    const __half* Ap = att + (size_t)h * L * L + (size_t)(bm + lr) * L + lcu * 2;
    int wr = tid >> 2, wcu = (tid & 3) * 4;
    const __half* Wp = vt + (size_t)(h * HD + wr) * L + wcu * 2;

    unsigned da0 = (unsigned)__cvta_generic_to_shared(&As[0][lr][lcu]);
    unsigned dw0 = (unsigned)__cvta_generic_to_shared(&Ws[0][wr][wcu]);
    const unsigned a_off = 128 * 20 * 4;
    const unsigned w_off = 64 * 20 * 4;

    cp16(da0, Ap);      cp16(da0 + 16, Ap + 8);
    cp16(dw0, Wp);
    CP_COMMIT();

    for (int k0 = 0; k0 < L; k0 += 32) {     // halves
        int s = (k0 >> 5) & 1;
        if (k0 + 32 < L) {
            cp16(da0 + (s ^ 1) * a_off, Ap + k0 + 32);
            cp16(da0 + (s ^ 1) * a_off + 16, Ap + k0 + 40);
            cp16(dw0 + (s ^ 1) * w_off, Wp + k0 + 32);
            CP_COMMIT();
            CP_WAIT1();
        } else {
            CP_WAIT0();
        }
        __syncthreads();
#pragma unroll
        for (int kc = 0; kc < 2; kc++) {
            int kk = kc * 8;
            unsigned af[2][4], bf[4][2];
#pragma unroll
            for (int mt = 0; mt < 2; mt++) {
                int rm = wm * 32 + mt * 16 + g;
                af[mt][0] = As[s][rm][kk + c];
                af[mt][1] = As[s][rm + 8][kk + c];
                af[mt][2] = As[s][rm][kk + c + 4];
                af[mt][3] = As[s][rm + 8][kk + c + 4];
            }
#pragma unroll
            for (int nt = 0; nt < 4; nt++) {
                int rn = wn * 32 + nt * 8 + g;
                bf[nt][0] = Ws[s][rn][kk + c];
                bf[nt][1] = Ws[s][rn][kk + c + 4];
            }
#pragma unroll
            for (int mt = 0; mt < 2; mt++)
#pragma unroll
                for (int nt = 0; nt < 4; nt++)
                    mma_f16(acc[mt][nt], af[mt], bf[nt]);
        }
        __syncthreads();
    }
#pragma unroll
    for (int mt = 0; mt < 2; mt++) {
        int row = bm + wm * 32 + mt * 16 + g;
        float inv0 = 1.0f / ssum[(size_t)h * L + row];
        float inv1 = 1.0f / ssum[(size_t)h * L + row + 8];
#pragma unroll
        for (int nt = 0; nt < 4; nt++) {
            int col = h * HD + wn * 32 + nt * 8 + 2 * c;
            *(__half2*)&o[(size_t)row * VS + col] =
                __floats2half2_rn(acc[mt][nt][0] * inv0, acc[mt][nt][1] * inv0);
            *(__half2*)&o[(size_t)(row + 8) * VS + col] =
                __floats2half2_rn(acc[mt][nt][2] * inv1, acc[mt][nt][3] * inv1);
        }
    }
}

// ---------------- fp16 transpose: out[c][r] = in[r][c] ----------------------
__global__ void transpose_h(const __half* __restrict__ in, __half* __restrict__ out,
                            int R, int Cc) {
    __shared__ __half t[32][34];
    int c0 = blockIdx.x * 32, r0 = blockIdx.y * 32;
    int tx = threadIdx.x, ty = threadIdx.y;  // 32 x 8
#pragma unroll
    for (int i = 0; i < 4; i++)
        t[ty + i * 8][tx] = in[(size_t)(r0 + ty + i * 8) * Cc + c0 + tx];
    __syncthreads();
#pragma unroll
    for (int i = 0; i < 4; i++)
        out[(size_t)(c0 + ty + i * 8) * R + r0 + tx] = t[tx][ty + i * 8];
}

// ---------------- row softmax over 2048 cols (fp32 out, for sp bias) --------
__global__ void softmax_row2048(const float* __restrict__ in, float* __restrict__ out,
                                float outscale) {
    __shared__ float sred[8];
    size_t row = blockIdx.x;
    const float* p = in + row * 2048;
    float* o = out + row * 2048;
    int tid = threadIdx.x;
    float v[8];
    float4 a = *(const float4*)&p[tid * 8];
    float4 b = *(const float4*)&p[tid * 8 + 4];
    v[0] = a.x; v[1] = a.y; v[2] = a.z; v[3] = a.w;
    v[4] = b.x; v[5] = b.y; v[6] = b.z; v[7] = b.w;
    float m = v[0];
#pragma unroll
    for (int i = 1; i < 8; i++) m = fmaxf(m, v[i]);
    m = blockRedMax(m, sred);
    float s = 0.0f;
#pragma unroll
    for (int i = 0; i < 8; i++) { v[i] = __expf(v[i] - m); s += v[i]; }
    s = blockRedSum(s, sred);
    float inv = outscale / s;
    float4 oa, ob;
    oa.x = v[0] * inv; oa.y = v[1] * inv; oa.z = v[2] * inv; oa.w = v[3] * inv;
    ob.x = v[4] * inv; ob.y = v[5] * inv; ob.z = v[6] * inv; ob.w = v[7] * inv;
    *(float4*)&o[tid * 8] = oa;
    *(float4*)&o[tid * 8 + 4] = ob;
}

// ---------------- fused residual + LayerNorm (fp32 out + optional fp16) -----
__global__ void add_ln(const float* __restrict__ a, const float* __restrict__ b,
                       const float* __restrict__ g, const float* __restrict__ be,
                       float* __restrict__ out, __half* __restrict__ out16) {
    __shared__ float sred[8];
    int row = blockIdx.x;
    int tid = threadIdx.x;
    size_t base = (size_t)row * 1024 + tid * 4;
    float4 va = *(const float4*)&a[base];
    float4 vb = *(const float4*)&b[base];
    float4 s;
    s.x = va.x + vb.x; s.y = va.y + vb.y; s.z = va.z + vb.z; s.w = va.w + vb.w;
    float sum = s.x + s.y + s.z + s.w;
    float sq = s.x * s.x + s.y * s.y + s.z * s.z + s.w * s.w;
    sum = blockRedSum(sum, sred);
    sq = blockRedSum(sq, sred);
    float mean = sum * (1.0f / 1024.0f);
    float var = sq * (1.0f / 1024.0f) - mean * mean;
    float r = rsqrtf(var + 1e-5f);
    float4 vg = *(const float4*)&g[tid * 4];
    float4 vbe = *(const float4*)&be[tid * 4];
    float4 o;
    o.x = (s.x - mean) * r * vg.x + vbe.x;
    o.y = (s.y - mean) * r * vg.y + vbe.y;
    o.z = (s.z - mean) * r * vg.z + vbe.z;
    o.w = (s.w - mean) * r * vg.w + vbe.w;
    *(float4*)&out[base] = o;
    if (out16) {
        *(__half2*)&out16[base]     = __floats2half2_rn(o.x, o.y);
        *(__half2*)&out16[base + 2] = __floats2half2_rn(o.z, o.w);
    }
}

// ---------------- launch ----------------------------------------------------
extern "C" void kernel_launch(void* const* d_in, const int* in_sizes, int n_in,
                              void* d_out, int out_size) {
    const float* x   = (const float*)d_in[0];
    const float* sp  = (const float*)d_in[1];
    const float* Wq  = (const float*)d_in[2];
    const float* bq  = (const float*)d_in[3];
    const float* Wk  = (const float*)d_in[4];
    const float* bk  = (const float*)d_in[5];
    const float* Wv  = (const float*)d_in[6];
    const float* bv  = (const float*)d_in[7];
    const float* Wqp = (const float*)d_in[8];
    const float* bqp = (const float*)d_in[9];
    const float* Wkp = (const float*)d_in[10];
    const float* bkp = (const float*)d_in[11];
    const float* Wvp = (const float*)d_in[12];
    const float* bvp = (const float*)d_in[13];
    const float* Wo  = (const float*)d_in[14];
    const float* bo  = (const float*)d_in[15];
    const float* W1  = (const float*)d_in[16];
    const float* b1  = (const float*)d_in[17];
    const float* W2  = (const float*)d_in[18];
    const float* b2  = (const float*)d_in[19];
    const float* g1  = (const float*)d_in[20];
    const float* be1 = (const float*)d_in[21];
    const float* g2  = (const float*)d_in[22];
    const float* be2 = (const float*)d_in[23];
    float* out = (float*)d_out;

    __half *pxh, *pwqh, *pwkh, *pwvh, *pwqph, *pwkph, *pwvph, *pwoh, *pw1h, *pw2h;
    __half *pt0h, *pqh, *pkh, *pvh, *pvth, *patt16, *poh, *phh;
    float *psp, *pssum, *ph, *pf;
    cudaGetSymbolAddress((void**)&pxh,   g_xh);
    cudaGetSymbolAddress((void**)&pwqh,  g_wqh);
    cudaGetSymbolAddress((void**)&pwkh,  g_wkh);
    cudaGetSymbolAddress((void**)&pwvh,  g_wvh);
    cudaGetSymbolAddress((void**)&pwqph, g_wqph);
    cudaGetSymbolAddress((void**)&pwkph, g_wkph);
    cudaGetSymbolAddress((void**)&pwvph, g_wvph);
    cudaGetSymbolAddress((void**)&pwoh,  g_woh);
    cudaGetSymbolAddress((void**)&pw1h,  g_w1h);
    cudaGetSymbolAddress((void**)&pw2h,  g_w2h);
    cudaGetSymbolAddress((void**)&pt0h,  g_t0h);
    cudaGetSymbolAddress((void**)&pqh,   g_qh);
    cudaGetSymbolAddress((void**)&pkh,   g_kh);
    cudaGetSymbolAddress((void**)&pvh,   g_vh);
    cudaGetSymbolAddress((void**)&pvth,  g_vth);
    cudaGetSymbolAddress((void**)&patt16, g_att16);
    cudaGetSymbolAddress((void**)&pssum, g_ssum);
    cudaGetSymbolAddress((void**)&poh,   g_oh);
    cudaGetSymbolAddress((void**)&phh,   g_hh);
    cudaGetSymbolAddress((void**)&psp,   g_sp);
    cudaGetSymbolAddress((void**)&ph,    g_h);
    cudaGetSymbolAddress((void**)&pf,    g_f);

    __half* t0a = pt0h;
    __half* t0b = pt0h + (size_t)L * KS;
    __half* t0c = pt0h + (size_t)2 * L * KS;

    dim3 blk256(256), blk512(512);

    // fp32 -> fp16 conversions (input + weights)
    f2h<<<(L * D) / 1024, 256>>>(x, pxh, L * D);
    f2h<<<(KS * D) / 1024, 256>>>(Wq, pwqh, KS * D);
    f2h<<<(KS * D) / 1024, 256>>>(Wk, pwkh, KS * D);
    f2h<<<(VS * D) / 1024, 256>>>(Wv, pwvh, VS * D);
    f2h<<<(KS * KS) / 1024, 256>>>(Wqp, pwqph, KS * KS);
    f2h<<<(KS * KS) / 1024, 256>>>(Wkp, pwkph, KS * KS);
    f2h<<<(VS * VS) / 1024, 256>>>(Wvp, pwvph, VS * VS);
    f2h<<<(D * VS) / 1024, 256>>>(Wo, pwoh, D * VS);
    f2h<<<(HID * D) / 1024, 256>>>(W1, pw1h, HID * D);
    f2h<<<(D * HID) / 1024, 256>>>(W2, pw2h, D * HID);

    // QKV stage-1 (shared A = xh), merged
    gemm_tc3<<<dim3(KS / 128, L / 128, 3), blk512>>>(
        pxh, pxh, pxh, pwqh, pwkh, pwvh, bq, bk, bv, t0a, t0b, t0c, KS, D);
    // QKV stage-2, merged
    gemm_tc3<<<dim3(KS / 128, L / 128, 3), blk512>>>(
        t0a, t0b, t0c, pwqph, pwkph, pwvph, bqp, bkp, bvp, pqh, pkh, pvh, KS, KS);

    // v transpose (fp16)
    transpose_h<<<dim3(VS / 32, L / 32), dim3(32, 8)>>>(pvh, pvth, L, VS);

    // sp_bias = 0.5 * softmax(shortest_path)
    softmax_row2048<<<L, blk256>>>(sp, psp, 0.5f);

    // fused scores + softmax: unnormalized fp16 probs + fp32 row sums
    attn_scores_softmax<<<dim3(L / 16, H), blk256>>>(pqh, pkh, psp, patt16, pssum);

    // context = (probs @ v) / ssum  (fp16 out)
    attn_av_tc<<<dim3(1, L / 128, H), blk256>>>(patt16, pvth, pssum, poh);

    // o-proj (fp32 out), residual + LN1 (fp32 + fp16 copies)
    gemm_tc<0, 0><<<dim3(D / 128, L / 128), blk512>>>(poh, pwoh, bo, pf, D, VS);
    add_ln<<<L, blk256>>>(x, pf, g1, be1, ph, phh);

    // FFN: hidden fp16, out fp32; residual + LN2 -> final fp32
    gemm_tc<1, 1><<<dim3(HID / 128, L / 128), blk512>>>(phh, pw1h, b1, pt0h, HID, D);
    gemm_tc<1, 0><<<dim3(D / 128, L / 128), blk512>>>(pt0h, pw2h, b2, pf, D, HID);
    add_ln<<<L, blk256>>>(ph, pf, g2, be2, out, (__half*)0);
}

// round 12
// speedup vs baseline: 2.3830x; 1.3761x over previous
#include <cuda_runtime.h>
#include <cuda_fp16.h>
#include <cstddef>
#include <cstdint>

#define L   2048
#define D   1024
#define H   16
#define KS  1024
#define VS  1024
#define HID 4096
#define HD  64

// ---------------- scratch (device globals; no allocation allowed) ----------
__device__ __half g_xh[L * D];
__device__ __half g_wqh[KS * D];
__device__ __half g_wkh[KS * D];
__device__ __half g_wvh[VS * D];
__device__ __half g_wqph[KS * KS];
__device__ __half g_wkph[KS * KS];
__device__ __half g_wvph[VS * VS];
__device__ __half g_woh[D * VS];
__device__ __half g_w1h[HID * D];
__device__ __half g_w2h[D * HID];
__device__ __half g_t0h[L * HID];              // qkv stage-1 (3 slices) / FFN hidden
__device__ __half g_qh[L * KS];
__device__ __half g_kh[L * KS];
__device__ __half g_vh[L * VS];
__device__ __half g_vth[VS * L];
__device__ __half g_oh[L * VS];
__device__ __half g_hh[L * D];
__device__ float  g_sp[L * L];
__device__ float  g_h[L * D];
__device__ float  g_f[L * D];

// ---------------- helpers ---------------------------------------------------
// m16n8k16 fp16 MMA, fp32 accumulate
__device__ __forceinline__ void mma_f16(float* c, const unsigned* a, const unsigned* b) {
    asm volatile(
        "mma.sync.aligned.m16n8k16.row.col.f32.f16.f16.f32 "
        "{%0,%1,%2,%3}, {%4,%5,%6,%7}, {%8,%9}, {%0,%1,%2,%3};\n"
        : "+f"(c[0]), "+f"(c[1]), "+f"(c[2]), "+f"(c[3])
        : "r"(a[0]), "r"(a[1]), "r"(a[2]), "r"(a[3]), "r"(b[0]), "r"(b[1]));
}

__device__ __forceinline__ unsigned packe(float lo, float hi) {
    __half2 h = __floats2half2_rn(lo, hi);
    return *(unsigned*)&h;
}

__device__ __forceinline__ void cp16(unsigned dst, const void* src) {
    asm volatile("cp.async.ca.shared.global [%0], [%1], 16;\n" :: "r"(dst), "l"(src));
}
#define CP_COMMIT() asm volatile("cp.async.commit_group;\n" ::: "memory")
#define CP_WAIT1()  asm volatile("cp.async.wait_group 1;\n" ::: "memory")
#define CP_WAIT0()  asm volatile("cp.async.wait_group 0;\n" ::: "memory")

__device__ __forceinline__ float warpRedSum(float v) {
#pragma unroll
    for (int o = 16; o > 0; o >>= 1) v += __shfl_xor_sync(0xffffffffu, v, o);
    return v;
}
__device__ __forceinline__ float warpRedMax(float v) {
#pragma unroll
    for (int o = 16; o > 0; o >>= 1) v = fmaxf(v, __shfl_xor_sync(0xffffffffu, v, o));
    return v;
}
__device__ __forceinline__ float blockRedSum(float v, float* sred) {
    int lane = threadIdx.x & 31, w = threadIdx.x >> 5;
    v = warpRedSum(v);
    if (lane == 0) sred[w] = v;
    __syncthreads();
    float r;
    if (threadIdx.x < 32) {
        r = (threadIdx.x < 8) ? sred[threadIdx.x] : 0.0f;
        r = warpRedSum(r);
        if (threadIdx.x == 0) sred[0] = r;
    }
    __syncthreads();
    r = sred[0];
    __syncthreads();
    return r;
}
__device__ __forceinline__ float blockRedMax(float v, float* sred) {
    int lane = threadIdx.x & 31, w = threadIdx.x >> 5;
    v = warpRedMax(v);
    if (lane == 0) sred[w] = v;
    __syncthreads();
    float r;
    if (threadIdx.x < 32) {
        r = (threadIdx.x < 8) ? sred[threadIdx.x] : -3.4e38f;
        r = warpRedMax(r);
        if (threadIdx.x == 0) sred[0] = r;
    }
    __syncthreads();
    r = sred[0];
    __syncthreads();
    return r;
}

// ---------------- fp32 -> fp16 converter ------------------------------------
__global__ void f2h(const float* __restrict__ in, __half* __restrict__ out, int n) {
    int i = (blockIdx.x * blockDim.x + threadIdx.x) * 4;
    if (i < n) {
        float4 v = *(const float4*)&in[i];
        *(__half2*)&out[i]     = __floats2half2_rn(v.x, v.y);
        *(__half2*)&out[i + 2] = __floats2half2_rn(v.z, v.w);
    }
}

// ---------------- FP16 NT GEMM body: 128x128 tile, BK=32 halves, 512 thr ----
template <int RELU, int OUT_HALF>
__device__ __forceinline__ void gemm_body(const __half* __restrict__ A,
                                          const __half* __restrict__ W,
                                          const float* __restrict__ bias,
                                          void* __restrict__ Cv, int N, int K) {
    __shared__ unsigned As[2][128][20];   // 16 data uints (32 halves) + 4 pad
    __shared__ unsigned Ws[2][128][20];
    int tid = threadIdx.x;
    int wid = tid >> 5, lane = tid & 31;
    int g = lane >> 2, c = lane & 3;
    int wm = wid >> 2, wn = wid & 3;
    int bm = blockIdx.y * 128, bn = blockIdx.x * 128;

    float acc[2][4][4] = {};

    int lrow = tid >> 2;            // 0..127
    int lcu = (tid & 3) * 4;        // uint col: 0,4,8,12 (16B chunks)
    const __half* Ap = A + (size_t)(bm + lrow) * K + lcu * 2;
    const __half* Wp = W + (size_t)(bn + lrow) * K + lcu * 2;

    unsigned da0 = (unsigned)__cvta_generic_to_shared(&As[0][lrow][lcu]);
    unsigned dw0 = (unsigned)__cvta_generic_to_shared(&Ws[0][lrow][lcu]);
    const unsigned stage_off = 128 * 20 * 4;

    cp16(da0, Ap);
    cp16(dw0, Wp);
    CP_COMMIT();

    for (int k0 = 0; k0 < K; k0 += 32) {      // halves
        int s = (k0 >> 5) & 1;
        if (k0 + 32 < K) {
            cp16(da0 + (s ^ 1) * stage_off, Ap + k0 + 32);
            cp16(dw0 + (s ^ 1) * stage_off, Wp + k0 + 32);
            CP_COMMIT();
            CP_WAIT1();
        } else {
            CP_WAIT0();
        }
        __syncthreads();
#pragma unroll
        for (int kc = 0; kc < 2; kc++) {      // two k16 chunks per 32-half step
            int kk = kc * 8;                  // uint offset
            unsigned af[2][4], bf[4][2];
#pragma unroll
            for (int mt = 0; mt < 2; mt++) {
                int rm = wm * 32 + mt * 16 + g;
                af[mt][0] = As[s][rm][kk + c];
                af[mt][1] = As[s][rm + 8][kk + c];
                af[mt][2] = As[s][rm][kk + c + 4];
                af[mt][3] = As[s][rm + 8][kk + c + 4];
            }
#pragma unroll
            for (int nt = 0; nt < 4; nt++) {
                int rn = wn * 32 + nt * 8 + g;
                bf[nt][0] = Ws[s][rn][kk + c];
                bf[nt][1] = Ws[s][rn][kk + c + 4];
            }
#pragma unroll
            for (int mt = 0; mt < 2; mt++)
#pragma unroll
                for (int nt = 0; nt < 4; nt++)
                    mma_f16(acc[mt][nt], af[mt], bf[nt]);
        }
        __syncthreads();
    }
#pragma unroll
    for (int mt = 0; mt < 2; mt++) {
        int row = bm + wm * 32 + mt * 16 + g;
#pragma unroll
        for (int nt = 0; nt < 4; nt++) {
            int col = bn + wn * 32 + nt * 8 + 2 * c;
            float2 bv = *(const float2*)&bias[col];
            float v0 = acc[mt][nt][0] + bv.x;
            float v1 = acc[mt][nt][1] + bv.y;
            float v2 = acc[mt][nt][2] + bv.x;
            float v3 = acc[mt][nt][3] + bv.y;
            if (RELU) {
                v0 = fmaxf(v0, 0.0f); v1 = fmaxf(v1, 0.0f);
                v2 = fmaxf(v2, 0.0f); v3 = fmaxf(v3, 0.0f);
            }
            if (OUT_HALF) {
                __half* Ch = (__half*)Cv;
                *(__half2*)&Ch[(size_t)row * N + col] = __floats2half2_rn(v0, v1);
                *(__half2*)&Ch[(size_t)(row + 8) * N + col] = __floats2half2_rn(v2, v3);
            } else {
                float* Cf = (float*)Cv;
                *(float2*)&Cf[(size_t)row * N + col] = make_float2(v0, v1);
                *(float2*)&Cf[(size_t)(row + 8) * N + col] = make_float2(v2, v3);
            }
        }
    }
}

template <int RELU, int OUT_HALF>
__global__ void __launch_bounds__(512)
gemm_tc(const __half* __restrict__ A, const __half* __restrict__ W,
        const float* __restrict__ bias, void* __restrict__ C, int N, int K) {
    gemm_body<RELU, OUT_HALF>(A, W, bias, C, N, K);
}

// Merged 3-way GEMM (fp16 out): blockIdx.z selects operands.
__global__ void __launch_bounds__(512)
gemm_tc3(const __half* __restrict__ A0, const __half* __restrict__ A1,
         const __half* __restrict__ A2,
         const __half* __restrict__ W0, const __half* __restrict__ W1,
         const __half* __restrict__ W2,
         const float* __restrict__ b0, const float* __restrict__ b1,
         const float* __restrict__ b2,
         __half* __restrict__ C0, __half* __restrict__ C1, __half* __restrict__ C2,
         int N, int K) {
    int z = blockIdx.z;
    const __half* A = (z == 0) ? A0 : (z == 1) ? A1 : A2;
    const __half* W = (z == 0) ? W0 : (z == 1) ? W1 : W2;
    const float* b = (z == 0) ? b0 : (z == 1) ? b1 : b2;
    __half* C = (z == 0) ? C0 : (z == 1) ? C1 : C2;
    gemm_body<0, 1>(A, W, b, (void*)C, N, K);
}

// ---------------- fully fused flash attention -------------------------------
// grid (L/128, H), 256 threads = 8 warps. Warp w owns q-rows bm+w*16..+15.
// Sweep KV in 64-wide chunks: S = QK^T (MMA) -> +bias, online softmax ->
// P (fp16, repacked from S accumulators, zero shuffles) -> O += P V (MMA),
// with O rescaled by exp(m_old - m_new) per chunk. Final O /= rowsum.
// vt is V transposed: vt[d][kv].
__global__ void __launch_bounds__(256)
attn_fused(const __half* __restrict__ q, const __half* __restrict__ k,
           const __half* __restrict__ vt, const float* __restrict__ sp,
           __half* __restrict__ o) {
    __shared__ unsigned Ks[64][36];   // 64 kv rows x 32 uints (64 halves) + pad
    __shared__ unsigned Vs[64][36];   // 64 d rows  x 32 uints (64 kv halves) + pad
    int tid = threadIdx.x;
    int w = tid >> 5, lane = tid & 31;
    int g = lane >> 2, c = lane & 3;
    int h = blockIdx.y;
    int bm = blockIdx.x * 128;
    int r0 = bm + w * 16 + g;        // "low" row; +8 is the "high" row

    // Q fragments for this warp's 16 rows (K=64 -> 4 k16 chunks)
    unsigned af[4][4];
    const __half* q0 = q + (size_t)r0 * KS + h * HD;
    const __half* q1 = q + (size_t)(r0 + 8) * KS + h * HD;
#pragma unroll
    for (int kc = 0; kc < 4; kc++) {
        af[kc][0] = *(const unsigned*)&q0[(kc * 8 + c) * 2];
        af[kc][1] = *(const unsigned*)&q1[(kc * 8 + c) * 2];
        af[kc][2] = *(const unsigned*)&q0[(kc * 8 + c + 4) * 2];
        af[kc][3] = *(const unsigned*)&q1[(kc * 8 + c + 4) * 2];
    }
    const float* sp0 = sp + (size_t)r0 * L;
    const float* sp1 = sp + (size_t)(r0 + 8) * L;

    float oacc[8][4] = {};
    float m0 = -3.4e38f, m1 = -3.4e38f;
    float l0 = 0.0f, l1 = 0.0f;

    for (int nb = 0; nb < L / 64; nb++) {
        __syncthreads();
        for (int i = tid; i < 512; i += 256) {
            int r = i >> 3, ch = i & 7;
            *(uint4*)&Ks[r][ch * 4] =
                *(const uint4*)&k[(size_t)(nb * 64 + r) * KS + h * HD + ch * 8];
            *(uint4*)&Vs[r][ch * 4] =
                *(const uint4*)&vt[(size_t)(h * HD + r) * L + nb * 64 + ch * 8];
        }
        __syncthreads();

        // S = Q K^T over this 64-kv chunk (8 n-tiles x 4 k-chunks)
        float sacc[8][4] = {};
#pragma unroll
        for (int kc = 0; kc < 4; kc++) {
            int kk = kc * 8;
#pragma unroll
            for (int nt = 0; nt < 8; nt++) {
                int rn = nt * 8 + g;
                unsigned bf[2] = {Ks[rn][kk + c], Ks[rn][kk + c + 4]};
                mma_f16(sacc[nt], af[kc], bf);
            }
        }
        // logits = S/8 + sp_bias; chunk max
        float cm0 = -3.4e38f, cm1 = -3.4e38f;
#pragma unroll
        for (int nt = 0; nt < 8; nt++) {
            int col = nb * 64 + nt * 8 + 2 * c;
            float2 s0 = *(const float2*)&sp0[col];
            float2 s1 = *(const float2*)&sp1[col];
            sacc[nt][0] = sacc[nt][0] * 0.125f + s0.x;
            sacc[nt][1] = sacc[nt][1] * 0.125f + s0.y;
            sacc[nt][2] = sacc[nt][2] * 0.125f + s1.x;
            sacc[nt][3] = sacc[nt][3] * 0.125f + s1.y;
            cm0 = fmaxf(cm0, fmaxf(sacc[nt][0], sacc[nt][1]));
            cm1 = fmaxf(cm1, fmaxf(sacc[nt][2], sacc[nt][3]));
        }
        cm0 = fmaxf(cm0, __shfl_xor_sync(0xffffffffu, cm0, 1));
        cm0 = fmaxf(cm0, __shfl_xor_sync(0xffffffffu, cm0, 2));
        cm1 = fmaxf(cm1, __shfl_xor_sync(0xffffffffu, cm1, 1));
        cm1 = fmaxf(cm1, __shfl_xor_sync(0xffffffffu, cm1, 2));
        float nm0 = fmaxf(m0, cm0), nm1 = fmaxf(m1, cm1);
        float sc0 = __expf(m0 - nm0), sc1 = __expf(m1 - nm1);
        m0 = nm0; m1 = nm1;
        l0 *= sc0; l1 *= sc1;
#pragma unroll
        for (int nt = 0; nt < 8; nt++) {
            oacc[nt][0] *= sc0; oacc[nt][1] *= sc0;
            oacc[nt][2] *= sc1; oacc[nt][3] *= sc1;
        }
        // exp -> fp16 P fragments (accumulator layout == A-fragment layout)
        unsigned pf[4][4];
#pragma unroll
        for (int nt = 0; nt < 8; nt++) {
            float e0 = __expf(sacc[nt][0] - m0);
            float e1 = __expf(sacc[nt][1] - m0);
            float e2 = __expf(sacc[nt][2] - m1);
            float e3 = __expf(sacc[nt][3] - m1);
            l0 += e0 + e1;
            l1 += e2 + e3;
            int kc = nt >> 1;
            if ((nt & 1) == 0) {
                pf[kc][0] = packe(e0, e1);
                pf[kc][1] = packe(e2, e3);
            } else {
                pf[kc][2] = packe(e0, e1);
                pf[kc][3] = packe(e2, e3);
            }
        }
        // O += P V (8 d-tiles x 4 kv k-chunks)
#pragma unroll
        for (int kc = 0; kc < 4; kc++) {
            int kk = kc * 8;
#pragma unroll
            for (int nt = 0; nt < 8; nt++) {
                int rn = nt * 8 + g;
                unsigned bf[2] = {Vs[rn][kk + c], Vs[rn][kk + c + 4]};
                mma_f16(oacc[nt], pf[kc], bf);
            }
        }
    }
    // finalize: reduce row sums across the c quad (column partition)
    l0 += __shfl_xor_sync(0xffffffffu, l0, 1);
    l0 += __shfl_xor_sync(0xffffffffu, l0, 2);
    l1 += __shfl_xor_sync(0xffffffffu, l1, 1);
    l1 += __shfl_xor_sync(0xffffffffu, l1, 2);
    float inv0 = 1.0f / l0, inv1 = 1.0f / l1;
#pragma unroll
    for (int nt = 0; nt < 8; nt++) {
        int col = h * HD + nt * 8 + 2 * c;
        *(__half2*)&o[(size_t)r0 * VS + col] =
            __floats2half2_rn(oacc[nt][0] * inv0, oacc[nt][1] * inv0);
        *(__half2*)&o[(size_t)(r0 + 8) * VS + col] =
            __floats2half2_rn(oacc[nt][2] * inv1, oacc[nt][3] * inv1);
    }
}

// ---------------- fp16 transpose: out[c][r] = in[r][c] ----------------------
__global__ void transpose_h(const __half* __restrict__ in, __half* __restrict__ out,
                            int R, int Cc) {
    __shared__ __half t[32][34];
    int c0 = blockIdx.x * 32, r0 = blockIdx.y * 32;
    int tx = threadIdx.x, ty = threadIdx.y;  // 32 x 8
#pragma unroll
    for (int i = 0; i < 4; i++)
        t[ty + i * 8][tx] = in[(size_t)(r0 + ty + i * 8) * Cc + c0 + tx];
    __syncthreads();
#pragma unroll
    for (int i = 0; i < 4; i++)
        out[(size_t)(c0 + ty + i * 8) * R + r0 + tx] = t[tx][ty + i * 8];
}

// ---------------- row softmax over 2048 cols (fp32 out, for sp bias) --------
__global__ void softmax_row2048(const float* __restrict__ in, float* __restrict__ out,
                                float outscale) {
    __shared__ float sred[8];
    size_t row = blockIdx.x;
    const float* p = in + row * 2048;
    float* o = out + row * 2048;
    int tid = threadIdx.x;
    float v[8];
    float4 a = *(const float4*)&p[tid * 8];
    float4 b = *(const float4*)&p[tid * 8 + 4];
    v[0] = a.x; v[1] = a.y; v[2] = a.z; v[3] = a.w;
    v[4] = b.x; v[5] = b.y; v[6] = b.z; v[7] = b.w;
    float m = v[0];
#pragma unroll
    for (int i = 1; i < 8; i++) m = fmaxf(m, v[i]);
    m = blockRedMax(m, sred);
    float s = 0.0f;
#pragma unroll
    for (int i = 0; i < 8; i++) { v[i] = __expf(v[i] - m); s += v[i]; }
    s = blockRedSum(s, sred);
    float inv = outscale / s;
    float4 oa, ob;
    oa.x = v[0] * inv; oa.y = v[1] * inv; oa.z = v[2] * inv; oa.w = v[3] * inv;
    ob.x = v[4] * inv; ob.y = v[5] * inv; ob.z = v[6] * inv; ob.w = v[7] * inv;
    *(float4*)&o[tid * 8] = oa;
    *(float4*)&o[tid * 8 + 4] = ob;
}

// ---------------- fused residual + LayerNorm (fp32 out + optional fp16) -----
__global__ void add_ln(const float* __restrict__ a, const float* __restrict__ b,
                       const float* __restrict__ g, const float* __restrict__ be,
                       float* __restrict__ out, __half* __restrict__ out16) {
    __shared__ float sred[8];
    int row = blockIdx.x;
    int tid = threadIdx.x;
    size_t base = (size_t)row * 1024 + tid * 4;
    float4 va = *(const float4*)&a[base];
    float4 vb = *(const float4*)&b[base];
    float4 s;
    s.x = va.x + vb.x; s.y = va.y + vb.y; s.z = va.z + vb.z; s.w = va.w + vb.w;
    float sum = s.x + s.y + s.z + s.w;
    float sq = s.x * s.x + s.y * s.y + s.z * s.z + s.w * s.w;
    sum = blockRedSum(sum, sred);
    sq = blockRedSum(sq, sred);
    float mean = sum * (1.0f / 1024.0f);
    float var = sq * (1.0f / 1024.0f) - mean * mean;
    float r = rsqrtf(var + 1e-5f);
    float4 vg = *(const float4*)&g[tid * 4];
    float4 vbe = *(const float4*)&be[tid * 4];
    float4 o;
    o.x = (s.x - mean) * r * vg.x + vbe.x;
    o.y = (s.y - mean) * r * vg.y + vbe.y;
    o.z = (s.z - mean) * r * vg.z + vbe.z;
    o.w = (s.w - mean) * r * vg.w + vbe.w;
    *(float4*)&out[base] = o;
    if (out16) {
        *(__half2*)&out16[base]     = __floats2half2_rn(o.x, o.y);
        *(__half2*)&out16[base + 2] = __floats2half2_rn(o.z, o.w);
    }
}

// ---------------- launch ----------------------------------------------------
extern "C" void kernel_launch(void* const* d_in, const int* in_sizes, int n_in,
                              void* d_out, int out_size) {
    const float* x   = (const float*)d_in[0];
    const float* sp  = (const float*)d_in[1];
    const float* Wq  = (const float*)d_in[2];
    const float* bq  = (const float*)d_in[3];
    const float* Wk  = (const float*)d_in[4];
    const float* bk  = (const float*)d_in[5];
    const float* Wv  = (const float*)d_in[6];
    const float* bv  = (const float*)d_in[7];
    const float* Wqp = (const float*)d_in[8];
    const float* bqp = (const float*)d_in[9];
    const float* Wkp = (const float*)d_in[10];
    const float* bkp = (const float*)d_in[11];
    const float* Wvp = (const float*)d_in[12];
    const float* bvp = (const float*)d_in[13];
    const float* Wo  = (const float*)d_in[14];
    const float* bo  = (const float*)d_in[15];
    const float* W1  = (const float*)d_in[16];
    const float* b1  = (const float*)d_in[17];
    const float* W2  = (const float*)d_in[18];
    const float* b2  = (const float*)d_in[19];
    const float* g1  = (const float*)d_in[20];
    const float* be1 = (const float*)d_in[21];
    const float* g2  = (const float*)d_in[22];
    const float* be2 = (const float*)d_in[23];
    float* out = (float*)d_out;

    __half *pxh, *pwqh, *pwkh, *pwvh, *pwqph, *pwkph, *pwvph, *pwoh, *pw1h, *pw2h;
    __half *pt0h, *pqh, *pkh, *pvh, *pvth, *poh, *phh;
    float *psp, *ph, *pf;
    cudaGetSymbolAddress((void**)&pxh,   g_xh);
    cudaGetSymbolAddress((void**)&pwqh,  g_wqh);
    cudaGetSymbolAddress((void**)&pwkh,  g_wkh);
    cudaGetSymbolAddress((void**)&pwvh,  g_wvh);
    cudaGetSymbolAddress((void**)&pwqph, g_wqph);
    cudaGetSymbolAddress((void**)&pwkph, g_wkph);
    cudaGetSymbolAddress((void**)&pwvph, g_wvph);
    cudaGetSymbolAddress((void**)&pwoh,  g_woh);
    cudaGetSymbolAddress((void**)&pw1h,  g_w1h);
    cudaGetSymbolAddress((void**)&pw2h,  g_w2h);
    cudaGetSymbolAddress((void**)&pt0h,  g_t0h);
    cudaGetSymbolAddress((void**)&pqh,   g_qh);
    cudaGetSymbolAddress((void**)&pkh,   g_kh);
    cudaGetSymbolAddress((void**)&pvh,   g_vh);
    cudaGetSymbolAddress((void**)&pvth,  g_vth);
    cudaGetSymbolAddress((void**)&poh,   g_oh);
    cudaGetSymbolAddress((void**)&phh,   g_hh);
    cudaGetSymbolAddress((void**)&psp,   g_sp);
    cudaGetSymbolAddress((void**)&ph,    g_h);
    cudaGetSymbolAddress((void**)&pf,    g_f);

    __half* t0a = pt0h;
    __half* t0b = pt0h + (size_t)L * KS;
    __half* t0c = pt0h + (size_t)2 * L * KS;

    dim3 blk256(256), blk512(512);

    // fp32 -> fp16 conversions (input + weights)
    f2h<<<(L * D) / 1024, 256>>>(x, pxh, L * D);
    f2h<<<(KS * D) / 1024, 256>>>(Wq, pwqh, KS * D);
    f2h<<<(KS * D) / 1024, 256>>>(Wk, pwkh, KS * D);
    f2h<<<(VS * D) / 1024, 256>>>(Wv, pwvh, VS * D);
    f2h<<<(KS * KS) / 1024, 256>>>(Wqp, pwqph, KS * KS);
    f2h<<<(KS * KS) / 1024, 256>>>(Wkp, pwkph, KS * KS);
    f2h<<<(VS * VS) / 1024, 256>>>(Wvp, pwvph, VS * VS);
    f2h<<<(D * VS) / 1024, 256>>>(Wo, pwoh, D * VS);
    f2h<<<(HID * D) / 1024, 256>>>(W1, pw1h, HID * D);
    f2h<<<(D * HID) / 1024, 256>>>(W2, pw2h, D * HID);

    // QKV stage-1 (shared A = xh), merged
    gemm_tc3<<<dim3(KS / 128, L / 128, 3), blk512>>>(
        pxh, pxh, pxh, pwqh, pwkh, pwvh, bq, bk, bv, t0a, t0b, t0c, KS, D);
    // QKV stage-2, merged
    gemm_tc3<<<dim3(KS / 128, L / 128, 3), blk512>>>(
        t0a, t0b, t0c, pwqph, pwkph, pwvph, bqp, bkp, bvp, pqh, pkh, pvh, KS, KS);

    // v transpose (fp16): vt[d][kv]
    transpose_h<<<dim3(VS / 32, L / 32), dim3(32, 8)>>>(pvh, pvth, L, VS);

    // sp_bias = 0.5 * softmax(shortest_path)
    softmax_row2048<<<L, blk256>>>(sp, psp, 0.5f);

    // fully fused attention: scores + online softmax + AV, fp16 out
    attn_fused<<<dim3(L / 128, H), blk256>>>(pqh, pkh, pvth, psp, poh);

    // o-proj (fp32 out), residual + LN1 (fp32 + fp16 copies)
    gemm_tc<0, 0><<<dim3(D / 128, L / 128), blk512>>>(poh, pwoh, bo, pf, D, VS);
    add_ln<<<L, blk256>>>(x, pf, g1, be1, ph, phh);

    // FFN: hidden fp16, out fp32; residual + LN2 -> final fp32
    gemm_tc<1, 1><<<dim3(HID / 128, L / 128), blk512>>>(phh, pw1h, b1, pt0h, HID, D);
    gemm_tc<1, 0><<<dim3(D / 128, L / 128), blk512>>>(pt0h, pw2h, b2, pf, D, HID);
    add_ln<<<L, blk256>>>(ph, pf, g2, be2, out, (__half*)0);
}

// round 14
// speedup vs baseline: 2.6697x; 1.1203x over previous
#include <cuda_runtime.h>
#include <cuda_fp16.h>
#include <cstddef>
#include <cstdint>

#define L   2048
#define D   1024
#define H   16
#define KS  1024
#define VS  1024
#define HID 4096
#define HD  64

// ---------------- scratch (device globals; no allocation allowed) ----------
__device__ __half g_xh[L * D];
__device__ __half g_wqh[KS * D];
__device__ __half g_wkh[KS * D];
__device__ __half g_wvh[VS * D];
__device__ __half g_wqph[KS * KS];
__device__ __half g_wkph[KS * KS];
__device__ __half g_wvph[VS * VS];
__device__ __half g_woh[D * VS];
__device__ __half g_w1h[HID * D];
__device__ __half g_w2h[D * HID];
__device__ __half g_t0h[L * HID];              // qkv stage-1 (3 slices) / FFN hidden
__device__ __half g_qh[L * KS];
__device__ __half g_kh[L * KS];
__device__ __half g_vh[L * VS];
__device__ __half g_vth[VS * L];
__device__ __half g_oh[L * VS];
__device__ __half g_hh[L * D];
__device__ float  g_sp[L * L];
__device__ float  g_h[L * D];
__device__ float  g_f[L * D];

// ---------------- helpers ---------------------------------------------------
// m16n8k16 fp16 MMA, fp32 accumulate
__device__ __forceinline__ void mma_f16(float* c, const unsigned* a, const unsigned* b) {
    asm volatile(
        "mma.sync.aligned.m16n8k16.row.col.f32.f16.f16.f32 "
        "{%0,%1,%2,%3}, {%4,%5,%6,%7}, {%8,%9}, {%0,%1,%2,%3};\n"
        : "+f"(c[0]), "+f"(c[1]), "+f"(c[2]), "+f"(c[3])
        : "r"(a[0]), "r"(a[1]), "r"(a[2]), "r"(a[3]), "r"(b[0]), "r"(b[1]));
}

// ldmatrix x4: four 8x8 b16 tiles; lane groups 0-7/8-15/16-23/24-31 give the
// row addresses of tiles 0..3; reg i holds tile i's fragment for this lane.
__device__ __forceinline__ void ldsm4(unsigned& r0, unsigned& r1,
                                      unsigned& r2, unsigned& r3, unsigned addr) {
    asm volatile("ldmatrix.sync.aligned.m8n8.x4.shared.b16 {%0,%1,%2,%3}, [%4];"
                 : "=r"(r0), "=r"(r1), "=r"(r2), "=r"(r3) : "r"(addr));
}

__device__ __forceinline__ unsigned packe(float lo, float hi) {
    __half2 h = __floats2half2_rn(lo, hi);
    return *(unsigned*)&h;
}

__device__ __forceinline__ void cp16(unsigned dst, const void* src) {
    asm volatile("cp.async.ca.shared.global [%0], [%1], 16;\n" :: "r"(dst), "l"(src));
}
#define CP_COMMIT() asm volatile("cp.async.commit_group;\n" ::: "memory")
#define CP_WAIT1()  asm volatile("cp.async.wait_group 1;\n" ::: "memory")
#define CP_WAIT0()  asm volatile("cp.async.wait_group 0;\n" ::: "memory")

__device__ __forceinline__ float warpRedSum(float v) {
#pragma unroll
    for (int o = 16; o > 0; o >>= 1) v += __shfl_xor_sync(0xffffffffu, v, o);
    return v;
}
__device__ __forceinline__ float warpRedMax(float v) {
#pragma unroll
    for (int o = 16; o > 0; o >>= 1) v = fmaxf(v, __shfl_xor_sync(0xffffffffu, v, o));
    return v;
}
__device__ __forceinline__ float blockRedSum(float v, float* sred) {
    int lane = threadIdx.x & 31, w = threadIdx.x >> 5;
    v = warpRedSum(v);
    if (lane == 0) sred[w] = v;
    __syncthreads();
    float r;
    if (threadIdx.x < 32) {
        r = (threadIdx.x < 8) ? sred[threadIdx.x] : 0.0f;
        r = warpRedSum(r);
        if (threadIdx.x == 0) sred[0] = r;
    }
    __syncthreads();
    r = sred[0];
    __syncthreads();
    return r;
}
__device__ __forceinline__ float blockRedMax(float v, float* sred) {
    int lane = threadIdx.x & 31, w = threadIdx.x >> 5;
    v = warpRedMax(v);
    if (lane == 0) sred[w] = v;
    __syncthreads();
    float r;
    if (threadIdx.x < 32) {
        r = (threadIdx.x < 8) ? sred[threadIdx.x] : -3.4e38f;
        r = warpRedMax(r);
        if (threadIdx.x == 0) sred[0] = r;
    }
    __syncthreads();
    r = sred[0];
    __syncthreads();
    return r;
}

// ---------------- merged fp32 -> fp16 converter (all 10 arrays) -------------
struct F2HArgs {
    const float* src[10];
    __half* dst[10];
    unsigned off[11];   // cumulative element offsets
};
__global__ void f2h_all(F2HArgs a) {
    unsigned i = (blockIdx.x * blockDim.x + threadIdx.x) * 4;
    if (i >= a.off[10]) return;
#pragma unroll
    for (int sgi = 0; sgi < 10; sgi++) {
        if (i < a.off[sgi + 1]) {
            unsigned j = i - a.off[sgi];
            float4 v = *(const float4*)&a.src[sgi][j];
            *(__half2*)&a.dst[sgi][j]     = __floats2half2_rn(v.x, v.y);
            *(__half2*)&a.dst[sgi][j + 2] = __floats2half2_rn(v.z, v.w);
            return;
        }
    }
}

// ---------------- FP16 NT GEMM body: 128x128 tile, BK=32 halves, 512 thr ----
// Warps 4(m) x 4(n); warp tile 32x32. smem fp16 (uint = 2 halves), cp.async
// double-buffered. Fragments via ldmatrix.x4 (4 instr per k16 per warp).
template <int RELU, int OUT_HALF>
__device__ __forceinline__ void gemm_body(const __half* __restrict__ A,
                                          const __half* __restrict__ W,
                                          const float* __restrict__ bias,
                                          void* __restrict__ Cv, int N, int K) {
    __shared__ __align__(16) unsigned As[2][128][20];   // 16 data uints + 4 pad
    __shared__ __align__(16) unsigned Ws[2][128][20];
    int tid = threadIdx.x;
    int wid = tid >> 5, lane = tid & 31;
    int g = lane >> 2, c = lane & 3;
    int wm = wid >> 2, wn = wid & 3;
    int bm = blockIdx.y * 128, bn = blockIdx.x * 128;

    float acc[2][4][4] = {};

    int lrow = tid >> 2;            // 0..127
    int lcu = (tid & 3) * 4;        // uint col: 0,4,8,12 (16B chunks)
    const __half* Ap = A + (size_t)(bm + lrow) * K + lcu * 2;
    const __half* Wp = W + (size_t)(bn + lrow) * K + lcu * 2;

    unsigned da0 = (unsigned)__cvta_generic_to_shared(&As[0][lrow][lcu]);
    unsigned dw0 = (unsigned)__cvta_generic_to_shared(&Ws[0][lrow][lcu]);
    const unsigned stage_off = 128 * 20 * 4;

    // per-lane ldmatrix addresses (stage 0, kc 0)
    int m4 = lane >> 3;            // matrix index 0..3
    int l7 = lane & 7;
    unsigned a_base[2], b_base[2];
#pragma unroll
    for (int mt = 0; mt < 2; mt++) {
        int row = wm * 32 + mt * 16 + ((m4 & 1) ? 8 : 0) + l7;
        int col = (m4 >> 1) * 4;
        a_base[mt] = (unsigned)__cvta_generic_to_shared(&As[0][row][col]);
    }
#pragma unroll
    for (int p = 0; p < 2; p++) {
        int row = wn * 32 + p * 16 + ((m4 >> 1) ? 8 : 0) + l7;
        int col = (m4 & 1) * 4;
        b_base[p] = (unsigned)__cvta_generic_to_shared(&Ws[0][row][col]);
    }

    cp16(da0, Ap);
    cp16(dw0, Wp);
    CP_COMMIT();

    for (int k0 = 0; k0 < K; k0 += 32) {      // halves
        int s = (k0 >> 5) & 1;
        if (k0 + 32 < K) {
            cp16(da0 + (s ^ 1) * stage_off, Ap + k0 + 32);
            cp16(dw0 + (s ^ 1) * stage_off, Wp + k0 + 32);
            CP_COMMIT();
            CP_WAIT1();
        } else {
            CP_WAIT0();
        }
        __syncthreads();
        unsigned soff = s * stage_off;
#pragma unroll
        for (int kc = 0; kc < 2; kc++) {      // two k16 chunks per 32-half step
            unsigned ko = soff + kc * 32;     // 8 uints = 32 bytes
            unsigned af[2][4], bf[4][2];
#pragma unroll
            for (int mt = 0; mt < 2; mt++)
                ldsm4(af[mt][0], af[mt][1], af[mt][2], af[mt][3], a_base[mt] + ko);
#pragma unroll
            for (int p = 0; p < 2; p++)
                ldsm4(bf[2 * p][0], bf[2 * p][1], bf[2 * p + 1][0], bf[2 * p + 1][1],
                      b_base[p] + ko);
#pragma unroll
            for (int mt = 0; mt < 2; mt++)
#pragma unroll
                for (int nt = 0; nt < 4; nt++)
                    mma_f16(acc[mt][nt], af[mt], bf[nt]);
        }
        __syncthreads();
    }
#pragma unroll
    for (int mt = 0; mt < 2; mt++) {
        int row = bm + wm * 32 + mt * 16 + g;
#pragma unroll
        for (int nt = 0; nt < 4; nt++) {
            int col = bn + wn * 32 + nt * 8 + 2 * c;
            float2 bv = *(const float2*)&bias[col];
            float v0 = acc[mt][nt][0] + bv.x;
            float v1 = acc[mt][nt][1] + bv.y;
            float v2 = acc[mt][nt][2] + bv.x;
            float v3 = acc[mt][nt][3] + bv.y;
            if (RELU) {
                v0 = fmaxf(v0, 0.0f); v1 = fmaxf(v1, 0.0f);
                v2 = fmaxf(v2, 0.0f); v3 = fmaxf(v3, 0.0f);
            }
            if (OUT_HALF) {
                __half* Ch = (__half*)Cv;
                *(__half2*)&Ch[(size_t)row * N + col] = __floats2half2_rn(v0, v1);
                *(__half2*)&Ch[(size_t)(row + 8) * N + col] = __floats2half2_rn(v2, v3);
            } else {
                float* Cf = (float*)Cv;
                *(float2*)&Cf[(size_t)row * N + col] = make_float2(v0, v1);
                *(float2*)&Cf[(size_t)(row + 8) * N + col] = make_float2(v2, v3);
            }
        }
    }
}

template <int RELU, int OUT_HALF>
__global__ void __launch_bounds__(512)
gemm_tc(const __half* __restrict__ A, const __half* __restrict__ W,
        const float* __restrict__ bias, void* __restrict__ C, int N, int K) {
    gemm_body<RELU, OUT_HALF>(A, W, bias, C, N, K);
}

// Merged 3-way GEMM (fp16 out): blockIdx.z selects operands.
__global__ void __launch_bounds__(512)
gemm_tc3(const __half* __restrict__ A0, const __half* __restrict__ A1,
         const __half* __restrict__ A2,
         const __half* __restrict__ W0, const __half* __restrict__ W1,
         const __half* __restrict__ W2,
         const float* __restrict__ b0, const float* __restrict__ b1,
         const float* __restrict__ b2,
         __half* __restrict__ C0, __half* __restrict__ C1, __half* __restrict__ C2,
         int N, int K) {
    int z = blockIdx.z;
    const __half* A = (z == 0) ? A0 : (z == 1) ? A1 : A2;
    const __half* W = (z == 0) ? W0 : (z == 1) ? W1 : W2;
    const float* b = (z == 0) ? b0 : (z == 1) ? b1 : b2;
    __half* C = (z == 0) ? C0 : (z == 1) ? C1 : C2;
    gemm_body<0, 1>(A, W, b, (void*)C, N, K);
}

// ---------------- fully fused flash attention (ldmatrix fragments) ----------
// grid (L/128, H), 256 threads = 8 warps. Warp w owns q-rows bm+w*16..+15.
__global__ void __launch_bounds__(256)
attn_fused(const __half* __restrict__ q, const __half* __restrict__ k,
           const __half* __restrict__ vt, const float* __restrict__ sp,
           __half* __restrict__ o) {
    __shared__ __align__(16) unsigned Ks[64][36];   // 64 rows x 32 uints + 4 pad
    __shared__ __align__(16) unsigned Vs[64][36];
    int tid = threadIdx.x;
    int w = tid >> 5, lane = tid & 31;
    int g = lane >> 2, c = lane & 3;
    int h = blockIdx.y;
    int bm = blockIdx.x * 128;
    int r0 = bm + w * 16 + g;

    // Q fragments (K=64 -> 4 k16 chunks), straight from gmem
    unsigned af[4][4];
    const __half* q0 = q + (size_t)r0 * KS + h * HD;
    const __half* q1 = q + (size_t)(r0 + 8) * KS + h * HD;
#pragma unroll
    for (int kc = 0; kc < 4; kc++) {
        af[kc][0] = *(const unsigned*)&q0[(kc * 8 + c) * 2];
        af[kc][1] = *(const unsigned*)&q1[(kc * 8 + c) * 2];
        af[kc][2] = *(const unsigned*)&q0[(kc * 8 + c + 4) * 2];
        af[kc][3] = *(const unsigned*)&q1[(kc * 8 + c + 4) * 2];
    }
    const float* sp0 = sp + (size_t)r0 * L;
    const float* sp1 = sp + (size_t)(r0 + 8) * L;

    // per-lane ldmatrix addresses for K/V tiles (pairs of n8 tiles)
    int m4 = lane >> 3, l7 = lane & 7;
    unsigned kb[4], vb[4];
#pragma unroll
    for (int p = 0; p < 4; p++) {
        int row = p * 16 + ((m4 >> 1) ? 8 : 0) + l7;
        int col = (m4 & 1) * 4;
        kb[p] = (unsigned)__cvta_generic_to_shared(&Ks[row][col]);
        vb[p] = (unsigned)__cvta_generic_to_shared(&Vs[row][col]);
    }

    float oacc[8][4] = {};
    float m0 = -3.4e38f, m1 = -3.4e38f;
    float l0 = 0.0f, l1 = 0.0f;

    for (int nb = 0; nb < L / 64; nb++) {
        __syncthreads();
        for (int i = tid; i < 512; i += 256) {
            int r = i >> 3, ch = i & 7;
            *(uint4*)&Ks[r][ch * 4] =
                *(const uint4*)&k[(size_t)(nb * 64 + r) * KS + h * HD + ch * 8];
            *(uint4*)&Vs[r][ch * 4] =
                *(const uint4*)&vt[(size_t)(h * HD + r) * L + nb * 64 + ch * 8];
        }
        __syncthreads();

        // S = Q K^T over this 64-kv chunk
        float sacc[8][4] = {};
#pragma unroll
        for (int kc = 0; kc < 4; kc++) {
            unsigned ko = kc * 32;
#pragma unroll
            for (int p = 0; p < 4; p++) {
                unsigned b0, b1, b2, b3;
                ldsm4(b0, b1, b2, b3, kb[p] + ko);
                unsigned bfa[2] = {b0, b1}, bfb[2] = {b2, b3};
                mma_f16(sacc[2 * p], af[kc], bfa);
                mma_f16(sacc[2 * p + 1], af[kc], bfb);
            }
        }
        // logits = S/8 + sp_bias; chunk max
        float cm0 = -3.4e38f, cm1 = -3.4e38f;
#pragma unroll
        for (int nt = 0; nt < 8; nt++) {
            int col = nb * 64 + nt * 8 + 2 * c;
            float2 s0 = *(const float2*)&sp0[col];
            float2 s1 = *(const float2*)&sp1[col];
            sacc[nt][0] = sacc[nt][0] * 0.125f + s0.x;
            sacc[nt][1] = sacc[nt][1] * 0.125f + s0.y;
            sacc[nt][2] = sacc[nt][2] * 0.125f + s1.x;
            sacc[nt][3] = sacc[nt][3] * 0.125f + s1.y;
            cm0 = fmaxf(cm0, fmaxf(sacc[nt][0], sacc[nt][1]));
            cm1 = fmaxf(cm1, fmaxf(sacc[nt][2], sacc[nt][3]));
        }
        cm0 = fmaxf(cm0, __shfl_xor_sync(0xffffffffu, cm0, 1));
        cm0 = fmaxf(cm0, __shfl_xor_sync(0xffffffffu, cm0, 2));
        cm1 = fmaxf(cm1, __shfl_xor_sync(0xffffffffu, cm1, 1));
        cm1 = fmaxf(cm1, __shfl_xor_sync(0xffffffffu, cm1, 2));
        float nm0 = fmaxf(m0, cm0), nm1 = fmaxf(m1, cm1);
        float sc0 = __expf(m0 - nm0), sc1 = __expf(m1 - nm1);
        m0 = nm0; m1 = nm1;
        l0 *= sc0; l1 *= sc1;
#pragma unroll
        for (int nt = 0; nt < 8; nt++) {
            oacc[nt][0] *= sc0; oacc[nt][1] *= sc0;
            oacc[nt][2] *= sc1; oacc[nt][3] *= sc1;
        }
        // exp -> fp16 P fragments (accumulator layout == A-fragment layout)
        unsigned pf[4][4];
#pragma unroll
        for (int nt = 0; nt < 8; nt++) {
            float e0 = __expf(sacc[nt][0] - m0);
            float e1 = __expf(sacc[nt][1] - m0);
            float e2 = __expf(sacc[nt][2] - m1);
            float e3 = __expf(sacc[nt][3] - m1);
            l0 += e0 + e1;
            l1 += e2 + e3;
            int kc = nt >> 1;
            if ((nt & 1) == 0) {
                pf[kc][0] = packe(e0, e1);
                pf[kc][1] = packe(e2, e3);
            } else {
                pf[kc][2] = packe(e0, e1);
                pf[kc][3] = packe(e2, e3);
            }
        }
        // O += P V
#pragma unroll
        for (int kc = 0; kc < 4; kc++) {
            unsigned ko = kc * 32;
#pragma unroll
            for (int p = 0; p < 4; p++) {
                unsigned b0, b1, b2, b3;
                ldsm4(b0, b1, b2, b3, vb[p] + ko);
                unsigned bfa[2] = {b0, b1}, bfb[2] = {b2, b3};
                mma_f16(oacc[2 * p], pf[kc], bfa);
                mma_f16(oacc[2 * p + 1], pf[kc], bfb);
            }
        }
    }
    // finalize
    l0 += __shfl_xor_sync(0xffffffffu, l0, 1);
    l0 += __shfl_xor_sync(0xffffffffu, l0, 2);
    l1 += __shfl_xor_sync(0xffffffffu, l1, 1);
    l1 += __shfl_xor_sync(0xffffffffu, l1, 2);
    float inv0 = 1.0f / l0, inv1 = 1.0f / l1;
#pragma unroll
    for (int nt = 0; nt < 8; nt++) {
        int col = h * HD + nt * 8 + 2 * c;
        *(__half2*)&o[(size_t)r0 * VS + col] =
            __floats2half2_rn(oacc[nt][0] * inv0, oacc[nt][1] * inv0);
        *(__half2*)&o[(size_t)(r0 + 8) * VS + col] =
            __floats2half2_rn(oacc[nt][2] * inv1, oacc[nt][3] * inv1);
    }
}

// ---------------- fp16 transpose: out[c][r] = in[r][c] ----------------------
__global__ void transpose_h(const __half* __restrict__ in, __half* __restrict__ out,
                            int R, int Cc) {
    __shared__ __half t[32][34];
    int c0 = blockIdx.x * 32, r0 = blockIdx.y * 32;
    int tx = threadIdx.x, ty = threadIdx.y;  // 32 x 8
#pragma unroll
    for (int i = 0; i < 4; i++)
        t[ty + i * 8][tx] = in[(size_t)(r0 + ty + i * 8) * Cc + c0 + tx];
    __syncthreads();
#pragma unroll
    for (int i = 0; i < 4; i++)
        out[(size_t)(c0 + ty + i * 8) * R + r0 + tx] = t[tx][ty + i * 8];
}

// ---------------- row softmax over 2048 cols (fp32 out, for sp bias) --------
__global__ void softmax_row2048(const float* __restrict__ in, float* __restrict__ out,
                                float outscale) {
    __shared__ float sred[8];
    size_t row = blockIdx.x;
    const float* p = in + row * 2048;
    float* o = out + row * 2048;
    int tid = threadIdx.x;
    float v[8];
    float4 a = *(const float4*)&p[tid * 8];
    float4 b = *(const float4*)&p[tid * 8 + 4];
    v[0] = a.x; v[1] = a.y; v[2] = a.z; v[3] = a.w;
    v[4] = b.x; v[5] = b.y; v[6] = b.z; v[7] = b.w;
    float m = v[0];
#pragma unroll
    for (int i = 1; i < 8; i++) m = fmaxf(m, v[i]);
    m = blockRedMax(m, sred);
    float s = 0.0f;
#pragma unroll
    for (int i = 0; i < 8; i++) { v[i] = __expf(v[i] - m); s += v[i]; }
    s = blockRedSum(s, sred);
    float inv = outscale / s;
    float4 oa, ob;
    oa.x = v[0] * inv; oa.y = v[1] * inv; oa.z = v[2] * inv; oa.w = v[3] * inv;
    ob.x = v[4] * inv; ob.y = v[5] * inv; ob.z = v[6] * inv; ob.w = v[7] * inv;
    *(float4*)&o[tid * 8] = oa;
    *(float4*)&o[tid * 8 + 4] = ob;
}

// ---------------- fused residual + LayerNorm (fp32 out + optional fp16) -----
__global__ void add_ln(const float* __restrict__ a, const float* __restrict__ b,
                       const float* __restrict__ g, const float* __restrict__ be,
                       float* __restrict__ out, __half* __restrict__ out16) {
    __shared__ float sred[8];
    int row = blockIdx.x;
    int tid = threadIdx.x;
    size_t base = (size_t)row * 1024 + tid * 4;
    float4 va = *(const float4*)&a[base];
    float4 vb = *(const float4*)&b[base];
    float4 s;
    s.x = va.x + vb.x; s.y = va.y + vb.y; s.z = va.z + vb.z; s.w = va.w + vb.w;
    float sum = s.x + s.y + s.z + s.w;
    float sq = s.x * s.x + s.y * s.y + s.z * s.z + s.w * s.w;
    sum = blockRedSum(sum, sred);
    sq = blockRedSum(sq, sred);
    float mean = sum * (1.0f / 1024.0f);
    float var = sq * (1.0f / 1024.0f) - mean * mean;
    float r = rsqrtf(var + 1e-5f);
    float4 vg = *(const float4*)&g[tid * 4];
    float4 vbe = *(const float4*)&be[tid * 4];
    float4 o;
    o.x = (s.x - mean) * r * vg.x + vbe.x;
    o.y = (s.y - mean) * r * vg.y + vbe.y;
    o.z = (s.z - mean) * r * vg.z + vbe.z;
    o.w = (s.w - mean) * r * vg.w + vbe.w;
    *(float4*)&out[base] = o;
    if (out16) {
        *(__half2*)&out16[base]     = __floats2half2_rn(o.x, o.y);
        *(__half2*)&out16[base + 2] = __floats2half2_rn(o.z, o.w);
    }
}

// ---------------- launch ----------------------------------------------------
extern "C" void kernel_launch(void* const* d_in, const int* in_sizes, int n_in,
                              void* d_out, int out_size) {
    const float* x   = (const float*)d_in[0];
    const float* sp  = (const float*)d_in[1];
    const float* Wq  = (const float*)d_in[2];
    const float* bq  = (const float*)d_in[3];
    const float* Wk  = (const float*)d_in[4];
    const float* bk  = (const float*)d_in[5];
    const float* Wv  = (const float*)d_in[6];
    const float* bv  = (const float*)d_in[7];
    const float* Wqp = (const float*)d_in[8];
    const float* bqp = (const float*)d_in[9];
    const float* Wkp = (const float*)d_in[10];
    const float* bkp = (const float*)d_in[11];
    const float* Wvp = (const float*)d_in[12];
    const float* bvp = (const float*)d_in[13];
    const float* Wo  = (const float*)d_in[14];
    const float* bo  = (const float*)d_in[15];
    const float* W1  = (const float*)d_in[16];
    const float* b1  = (const float*)d_in[17];
    const float* W2  = (const float*)d_in[18];
    const float* b2  = (const float*)d_in[19];
    const float* g1  = (const float*)d_in[20];
    const float* be1 = (const float*)d_in[21];
    const float* g2  = (const float*)d_in[22];
    const float* be2 = (const float*)d_in[23];
    float* out = (float*)d_out;

    __half *pxh, *pwqh, *pwkh, *pwvh, *pwqph, *pwkph, *pwvph, *pwoh, *pw1h, *pw2h;
    __half *pt0h, *pqh, *pkh, *pvh, *pvth, *poh, *phh;
    float *psp, *ph, *pf;
    cudaGetSymbolAddress((void**)&pxh,   g_xh);
    cudaGetSymbolAddress((void**)&pwqh,  g_wqh);
    cudaGetSymbolAddress((void**)&pwkh,  g_wkh);
    cudaGetSymbolAddress((void**)&pwvh,  g_wvh);
    cudaGetSymbolAddress((void**)&pwqph, g_wqph);
    cudaGetSymbolAddress((void**)&pwkph, g_wkph);
    cudaGetSymbolAddress((void**)&pwvph, g_wvph);
    cudaGetSymbolAddress((void**)&pwoh,  g_woh);
    cudaGetSymbolAddress((void**)&pw1h,  g_w1h);
    cudaGetSymbolAddress((void**)&pw2h,  g_w2h);
    cudaGetSymbolAddress((void**)&pt0h,  g_t0h);
    cudaGetSymbolAddress((void**)&pqh,   g_qh);
    cudaGetSymbolAddress((void**)&pkh,   g_kh);
    cudaGetSymbolAddress((void**)&pvh,   g_vh);
    cudaGetSymbolAddress((void**)&pvth,  g_vth);
    cudaGetSymbolAddress((void**)&poh,   g_oh);
    cudaGetSymbolAddress((void**)&phh,   g_hh);
    cudaGetSymbolAddress((void**)&psp,   g_sp);
    cudaGetSymbolAddress((void**)&ph,    g_h);
    cudaGetSymbolAddress((void**)&pf,    g_f);

    __half* t0a = pt0h;
    __half* t0b = pt0h + (size_t)L * KS;
    __half* t0c = pt0h + (size_t)2 * L * KS;

    dim3 blk256(256), blk512(512);

    // single merged fp32 -> fp16 conversion pass
    F2HArgs fa;
    const float* srcs[10] = {x, Wq, Wk, Wv, Wqp, Wkp, Wvp, Wo, W1, W2};
    __half* dsts[10] = {pxh, pwqh, pwkh, pwvh, pwqph, pwkph, pwvph, pwoh, pw1h, pw2h};
    unsigned sizes[10] = {L * D, KS * D, KS * D, VS * D, KS * KS, KS * KS,
                          VS * VS, D * VS, HID * D, D * HID};
    unsigned acc = 0;
    for (int i = 0; i < 10; i++) {
        fa.src[i] = srcs[i];
        fa.dst[i] = dsts[i];
        fa.off[i] = acc;
        acc += sizes[i];
    }
    fa.off[10] = acc;
    f2h_all<<<(acc / 4 + 255) / 256, 256>>>(fa);

    // QKV stage-1 (shared A = xh), merged
    gemm_tc3<<<dim3(KS / 128, L / 128, 3), blk512>>>(
        pxh, pxh, pxh, pwqh, pwkh, pwvh, bq, bk, bv, t0a, t0b, t0c, KS, D);
    // QKV stage-2, merged
    gemm_tc3<<<dim3(KS / 128, L / 128, 3), blk512>>>(
        t0a, t0b, t0c, pwqph, pwkph, pwvph, bqp, bkp, bvp, pqh, pkh, pvh, KS, KS);

    // v transpose (fp16): vt[d][kv]
    transpose_h<<<dim3(VS / 32, L / 32), dim3(32, 8)>>>(pvh, pvth, L, VS);

    // sp_bias = 0.5 * softmax(shortest_path)
    softmax_row2048<<<L, blk256>>>(sp, psp, 0.5f);

    // fully fused attention: scores + online softmax + AV, fp16 out
    attn_fused<<<dim3(L / 128, H), blk256>>>(pqh, pkh, pvth, psp, poh);

    // o-proj (fp32 out), residual + LN1 (fp32 + fp16 copies)
    gemm_tc<0, 0><<<dim3(D / 128, L / 128), blk512>>>(poh, pwoh, bo, pf, D, VS);
    add_ln<<<L, blk256>>>(x, pf, g1, be1, ph, phh);

    // FFN: hidden fp16, out fp32; residual + LN2 -> final fp32
    gemm_tc<1, 1><<<dim3(HID / 128, L / 128), blk512>>>(phh, pw1h, b1, pt0h, HID, D);
    gemm_tc<1, 0><<<dim3(D / 128, L / 128), blk512>>>(pt0h, pw2h, b2, pf, D, HID);
    add_ln<<<L, blk256>>>(ph, pf, g2, be2, out, (__half*)0);
}